// round 1
// baseline (speedup 1.0000x reference)
#include <cuda_runtime.h>
#include <cuda_bf16.h>
#include <cstdint>

// Problem constants
#define BB      2
#define TT      8192
#define DD      1024
#define HH      8
#define DK      128
#define DV      128
#define CH      64
#define NCH     128           // chunks per sequence (8192/64)
#define BHN     16            // B*H
#define TTOT    16384         // B*T rows
#define NCHUNKS 2048          // B*H*NCH

// -------- scratch (device globals; no allocation allowed) --------
__device__ float g_q [TTOT * DD];
__device__ float g_k [TTOT * DD];
__device__ float g_v [TTOT * DD];
__device__ float g_fq[TTOT * DD];
__device__ float g_fk[TTOT * DD];
__device__ float g_o [TTOT * DD];
__device__ float g_S [(size_t)NCHUNKS * DK * DV];   // per-chunk kv, converted in-place to exclusive prefix
__device__ float g_Z [(size_t)NCHUNKS * DK];        // per-chunk ksum, converted in-place to exclusive prefix

// ============================================================================
// SGEMM: C[M,N] = A[M,K] @ B[K,N], all row-major. 128x128 tile, BK=16,
// 256 threads, 8x8 per thread. Assumes M%128==0, N%128==0, K%16==0.
// ============================================================================
__global__ void __launch_bounds__(256) sgemm_kernel(
    const float* __restrict__ A, const float* __restrict__ B,
    float* __restrict__ C, int M, int N, int K)
{
    __shared__ float As[16][128];
    __shared__ float Bs[16][128];

    const int tid = threadIdx.x;
    const int tx = tid & 15;
    const int ty = tid >> 4;
    const int rowBase = blockIdx.y * 128;
    const int colBase = blockIdx.x * 128;

    float acc[8][8];
    #pragma unroll
    for (int i = 0; i < 8; i++)
        #pragma unroll
        for (int j = 0; j < 8; j++) acc[i][j] = 0.f;

    for (int kt = 0; kt < K; kt += 16) {
        // load A tile (128x16) transposed into As[16][128]
        #pragma unroll
        for (int i = 0; i < 2; i++) {
            int lin = tid + i * 256;                  // 0..511
            int ar  = lin >> 2;                       // 0..127
            int ac  = (lin & 3) << 2;                 // 0,4,8,12
            float4 a4 = *(const float4*)&A[(size_t)(rowBase + ar) * K + kt + ac];
            As[ac + 0][ar] = a4.x;
            As[ac + 1][ar] = a4.y;
            As[ac + 2][ar] = a4.z;
            As[ac + 3][ar] = a4.w;
            int br = lin >> 5;                        // 0..15
            int bc = (lin & 31) << 2;                 // 0..124
            *(float4*)&Bs[br][bc] = *(const float4*)&B[(size_t)(kt + br) * N + colBase + bc];
        }
        __syncthreads();

        #pragma unroll
        for (int kk = 0; kk < 16; kk++) {
            float4 a0 = *(float4*)&As[kk][ty * 8];
            float4 a1 = *(float4*)&As[kk][ty * 8 + 4];
            float4 b0 = *(float4*)&Bs[kk][tx * 8];
            float4 b1 = *(float4*)&Bs[kk][tx * 8 + 4];
            float a[8] = {a0.x, a0.y, a0.z, a0.w, a1.x, a1.y, a1.z, a1.w};
            float b[8] = {b0.x, b0.y, b0.z, b0.w, b1.x, b1.y, b1.z, b1.w};
            #pragma unroll
            for (int i = 0; i < 8; i++)
                #pragma unroll
                for (int j = 0; j < 8; j++)
                    acc[i][j] = fmaf(a[i], b[j], acc[i][j]);
        }
        __syncthreads();
    }

    #pragma unroll
    for (int i = 0; i < 8; i++) {
        size_t r = (size_t)(rowBase + ty * 8 + i) * N + colBase + tx * 8;
        *(float4*)&C[r]     = make_float4(acc[i][0], acc[i][1], acc[i][2], acc[i][3]);
        *(float4*)&C[r + 4] = make_float4(acc[i][4], acc[i][5], acc[i][6], acc[i][7]);
    }
}

// ============================================================================
// Feature map: out = (in@W1 + b1) * (in@W2 + b2) * scale, per head.
// Block = 64 rows x 1 head (128 cols). 512 threads, each 4 rows x 4 cols.
// W1, W2 staged in SMEM (160 KB dynamic).
// ============================================================================
__global__ void __launch_bounds__(512) featmap_kernel(
    const float* __restrict__ in,
    const float* __restrict__ W1, const float* __restrict__ b1,
    const float* __restrict__ W2, const float* __restrict__ b2,
    float* __restrict__ out, float scale)
{
    extern __shared__ float sm[];
    float* x_s  = sm;           // 64*128 = 8192
    float* w1_s = sm + 8192;    // 128*128 = 16384
    float* w2_s = sm + 24576;   // 16384  -> total 40960 floats = 163840 B

    const int tid  = threadIdx.x;
    const int row0 = blockIdx.x * 64;
    const int h    = blockIdx.y;
    const size_t base = (size_t)row0 * DD + h * DK;

    #pragma unroll
    for (int i = 0; i < 4; i++) {
        int lin = tid + i * 512;          // 0..2047 float4s
        int rr = lin >> 5;                // 0..63
        int c  = (lin & 31) << 2;
        *(float4*)&x_s[rr * 128 + c] = *(const float4*)&in[base + (size_t)rr * DD + c];
    }
    #pragma unroll
    for (int i = 0; i < 8; i++) {
        int lin = tid + i * 512;          // 0..4095 float4s
        int rr = lin >> 5;                // 0..127
        int c  = (lin & 31) << 2;
        *(float4*)&w1_s[rr * 128 + c] = *(const float4*)&W1[rr * 128 + c];
        *(float4*)&w2_s[rr * 128 + c] = *(const float4*)&W2[rr * 128 + c];
    }
    __syncthreads();

    const int c0 = (tid & 31) * 4;        // col group
    const int r0 = (tid >> 5) * 4;        // row group

    float a1[4][4], a2[4][4];
    #pragma unroll
    for (int i = 0; i < 4; i++)
        #pragma unroll
        for (int j = 0; j < 4; j++) { a1[i][j] = 0.f; a2[i][j] = 0.f; }

    for (int k = 0; k < 128; k++) {
        float4 w1 = *(float4*)&w1_s[k * 128 + c0];
        float4 w2 = *(float4*)&w2_s[k * 128 + c0];
        #pragma unroll
        for (int i = 0; i < 4; i++) {
            float xv = x_s[(r0 + i) * 128 + k];
            a1[i][0] = fmaf(xv, w1.x, a1[i][0]);
            a1[i][1] = fmaf(xv, w1.y, a1[i][1]);
            a1[i][2] = fmaf(xv, w1.z, a1[i][2]);
            a1[i][3] = fmaf(xv, w1.w, a1[i][3]);
            a2[i][0] = fmaf(xv, w2.x, a2[i][0]);
            a2[i][1] = fmaf(xv, w2.y, a2[i][1]);
            a2[i][2] = fmaf(xv, w2.z, a2[i][2]);
            a2[i][3] = fmaf(xv, w2.w, a2[i][3]);
        }
    }

    float4 bb1 = *(const float4*)&b1[c0];
    float4 bb2 = *(const float4*)&b2[c0];
    #pragma unroll
    for (int i = 0; i < 4; i++) {
        float4 o;
        o.x = (a1[i][0] + bb1.x) * (a2[i][0] + bb2.x) * scale;
        o.y = (a1[i][1] + bb1.y) * (a2[i][1] + bb2.y) * scale;
        o.z = (a1[i][2] + bb1.z) * (a2[i][2] + bb2.z) * scale;
        o.w = (a1[i][3] + bb1.w) * (a2[i][3] + bb2.w) * scale;
        *(float4*)&out[base + (size_t)(r0 + i) * DD + c0] = o;
    }
}

// ============================================================================
// Per-chunk kv = fk^T @ v  (128x128, K=64) and ksum. grid (NCH, BHN), 256 thr.
// ============================================================================
__global__ void __launch_bounds__(256) chunk_kv_kernel()
{
    extern __shared__ float sm[];
    float* k_s = sm;            // 64*128 = 8192
    float* v_s = sm + 8192;     // 8192  -> 65536 B

    const int tid = threadIdx.x;
    const int n  = blockIdx.x;
    const int bh = blockIdx.y;
    const int b  = bh >> 3, h = bh & 7;
    const int row0 = b * TT + n * CH;
    const int col0 = h * DK;

    #pragma unroll
    for (int i = 0; i < 8; i++) {
        int lin = tid + i * 256;          // 0..2047 float4s
        int r = lin >> 5;
        int c = (lin & 31) << 2;
        size_t src = (size_t)(row0 + r) * DD + col0 + c;
        *(float4*)&k_s[r * 128 + c] = *(const float4*)&g_fk[src];
        *(float4*)&v_s[r * 128 + c] = *(const float4*)&g_v[src];
    }
    __syncthreads();

    const int d0 = (tid >> 4) * 8;
    const int e0 = (tid & 15) * 8;
    float acc[8][8];
    #pragma unroll
    for (int i = 0; i < 8; i++)
        #pragma unroll
        for (int j = 0; j < 8; j++) acc[i][j] = 0.f;

    for (int t = 0; t < 64; t++) {
        float4 ka = *(float4*)&k_s[t * 128 + d0];
        float4 kb = *(float4*)&k_s[t * 128 + d0 + 4];
        float4 va = *(float4*)&v_s[t * 128 + e0];
        float4 vb = *(float4*)&v_s[t * 128 + e0 + 4];
        float kk[8] = {ka.x, ka.y, ka.z, ka.w, kb.x, kb.y, kb.z, kb.w};
        float vv[8] = {va.x, va.y, va.z, va.w, vb.x, vb.y, vb.z, vb.w};
        #pragma unroll
        for (int i = 0; i < 8; i++)
            #pragma unroll
            for (int j = 0; j < 8; j++)
                acc[i][j] = fmaf(kk[i], vv[j], acc[i][j]);
    }

    size_t sb = ((size_t)bh * NCH + n) * (DK * DV);
    #pragma unroll
    for (int i = 0; i < 8; i++) {
        *(float4*)&g_S[sb + (size_t)(d0 + i) * DV + e0]     = make_float4(acc[i][0], acc[i][1], acc[i][2], acc[i][3]);
        *(float4*)&g_S[sb + (size_t)(d0 + i) * DV + e0 + 4] = make_float4(acc[i][4], acc[i][5], acc[i][6], acc[i][7]);
    }

    if (tid < 128) {
        float s = 0.f;
        for (int t = 0; t < 64; t++) s += k_s[t * 128 + tid];
        g_Z[((size_t)bh * NCH + n) * DK + tid] = s;
    }
}

// ============================================================================
// Exclusive prefix scan over chunks (in place): S and Z. grid (64, BHN), 256 thr.
// ============================================================================
__global__ void __launch_bounds__(256) scan_kernel()
{
    const int bh  = blockIdx.y;
    const int idx = blockIdx.x * 256 + threadIdx.x;   // 0..16383 element of 128x128

    float run = 0.f;
    size_t base = (size_t)bh * NCH * (DK * DV) + idx;
    for (int n = 0; n < NCH; n++) {
        size_t a = base + (size_t)n * (DK * DV);
        float t = g_S[a];
        g_S[a] = run;
        run += t;
    }
    if (blockIdx.x == 0 && threadIdx.x < DK) {
        float rz = 0.f;
        size_t zb = (size_t)bh * NCH * DK + threadIdx.x;
        for (int n = 0; n < NCH; n++) {
            size_t a = zb + (size_t)n * DK;
            float t = g_Z[a];
            g_Z[a] = rz;
            rz += t;
        }
    }
}

// ============================================================================
// Per-chunk output: o = tril(q k^T) v + q @ S ; den = rowsum + q.Z ;
// normalize by den, RMSNorm over DV, scale by g_w. grid (NCH, BHN), 256 thr.
// SMEM padded (row stride 132 / 65) to avoid LDS bank conflicts.
// ============================================================================
#define QS 132   // padded row stride for q/k/v/S tiles
#define AS 65    // padded row stride for attn

__global__ void __launch_bounds__(256) chunk_out_kernel(const float* __restrict__ g_w)
{
    extern __shared__ float sm[];
    float* q_s    = sm;                         // 64*132  = 8448
    float* k_s    = sm + 8448;                  // 8448 (reused as o_s)
    float* v_s    = sm + 16896;                 // 8448
    float* S_s    = sm + 25344;                 // 128*132 = 16896
    float* attn_s = sm + 42240;                 // 64*65   = 4160
    float* Z_s    = sm + 46400;                 // 128
    float* den_s  = sm + 46528;                 // 256
    float* red_s  = sm + 46784;                 // 256 -> total 47040 floats = 188160 B

    const int tid = threadIdx.x;
    const int n  = blockIdx.x;
    const int bh = blockIdx.y;
    const int b  = bh >> 3, h = bh & 7;
    const int row0 = b * TT + n * CH;
    const int col0 = h * DK;

    // ---- loads ----
    #pragma unroll
    for (int i = 0; i < 8; i++) {
        int lin = tid + i * 256;          // 0..2047 float4s
        int r = lin >> 5;
        int c = (lin & 31) << 2;
        size_t src = (size_t)(row0 + r) * DD + col0 + c;
        *(float4*)&q_s[r * QS + c] = *(const float4*)&g_fq[src];
        *(float4*)&k_s[r * QS + c] = *(const float4*)&g_fk[src];
        *(float4*)&v_s[r * QS + c] = *(const float4*)&g_v[src];
    }
    size_t sbase = ((size_t)bh * NCH + n) * (DK * DV);
    #pragma unroll
    for (int i = 0; i < 16; i++) {
        int lin = tid + i * 256;          // 0..4095 float4s
        int d = lin >> 5;
        int c = (lin & 31) << 2;
        *(float4*)&S_s[d * QS + c] = *(const float4*)&g_S[sbase + (size_t)d * DV + c];
    }
    if (tid < 32)
        *(float4*)&Z_s[tid * 4] = *(const float4*)&g_Z[((size_t)bh * NCH + n) * DK + tid * 4];
    __syncthreads();

    // ---- phase 1: attn (tril) + denominator partials ----
    const int r  = tid >> 2;
    const int mq = tid & 3;
    {
        float denp = 0.f;
        for (int mm = 0; mm < 16; mm++) {
            int m = mq * 16 + mm;
            float a = 0.f;
            if (m <= r) {
                #pragma unroll 8
                for (int d4 = 0; d4 < 32; d4++) {
                    float4 qv = *(float4*)&q_s[r * QS + d4 * 4];
                    float4 kv = *(float4*)&k_s[m * QS + d4 * 4];
                    a += qv.x * kv.x + qv.y * kv.y + qv.z * kv.z + qv.w * kv.w;
                }
                denp += a;
            }
            attn_s[r * AS + m] = (m <= r) ? a : 0.f;
        }
        // inter-chunk denominator: q . Z (split across 4 threads per row)
        #pragma unroll 8
        for (int d = mq * 32; d < mq * 32 + 32; d++)
            denp += q_s[r * QS + d] * Z_s[d];
        den_s[tid] = denp;
    }
    __syncthreads();

    // ---- phase 2: o = attn @ v + q @ S  (4 rows x 8 cols per thread) ----
    const int ty = tid >> 4;
    const int tx = tid & 15;
    const int e0 = tx * 8;
    float acc[4][8];
    #pragma unroll
    for (int i = 0; i < 4; i++)
        #pragma unroll
        for (int j = 0; j < 8; j++) acc[i][j] = 0.f;

    for (int m = 0; m < 64; m++) {
        float4 va = *(float4*)&v_s[m * QS + e0];
        float4 vb = *(float4*)&v_s[m * QS + e0 + 4];
        #pragma unroll
        for (int i = 0; i < 4; i++) {
            float a = attn_s[(ty * 4 + i) * AS + m];
            acc[i][0] = fmaf(a, va.x, acc[i][0]);
            acc[i][1] = fmaf(a, va.y, acc[i][1]);
            acc[i][2] = fmaf(a, va.z, acc[i][2]);
            acc[i][3] = fmaf(a, va.w, acc[i][3]);
            acc[i][4] = fmaf(a, vb.x, acc[i][4]);
            acc[i][5] = fmaf(a, vb.y, acc[i][5]);
            acc[i][6] = fmaf(a, vb.z, acc[i][6]);
            acc[i][7] = fmaf(a, vb.w, acc[i][7]);
        }
    }
    for (int d = 0; d < 128; d++) {
        float4 sa = *(float4*)&S_s[d * QS + e0];
        float4 sb = *(float4*)&S_s[d * QS + e0 + 4];
        #pragma unroll
        for (int i = 0; i < 4; i++) {
            float qv = q_s[(ty * 4 + i) * QS + d];
            acc[i][0] = fmaf(qv, sa.x, acc[i][0]);
            acc[i][1] = fmaf(qv, sa.y, acc[i][1]);
            acc[i][2] = fmaf(qv, sa.z, acc[i][2]);
            acc[i][3] = fmaf(qv, sa.w, acc[i][3]);
            acc[i][4] = fmaf(qv, sb.x, acc[i][4]);
            acc[i][5] = fmaf(qv, sb.y, acc[i][5]);
            acc[i][6] = fmaf(qv, sb.z, acc[i][6]);
            acc[i][7] = fmaf(qv, sb.w, acc[i][7]);
        }
    }
    // write o into k_s storage (k no longer needed; barrier above guarantees safety)
    float* o_s = k_s;
    #pragma unroll
    for (int i = 0; i < 4; i++) {
        *(float4*)&o_s[(ty * 4 + i) * QS + e0]     = make_float4(acc[i][0], acc[i][1], acc[i][2], acc[i][3]);
        *(float4*)&o_s[(ty * 4 + i) * QS + e0 + 4] = make_float4(acc[i][4], acc[i][5], acc[i][6], acc[i][7]);
    }
    __syncthreads();

    // ---- phase 3: divide by den, RMSNorm, write out ----
    float den = den_s[r * 4 + 0] + den_s[r * 4 + 1] + den_s[r * 4 + 2] + den_s[r * 4 + 3];
    float dinv = 1.f / (den + 1e-6f);
    float pp = 0.f;
    #pragma unroll 8
    for (int e = mq * 32; e < mq * 32 + 32; e++) {
        float val = o_s[r * QS + e] * dinv;
        pp += val * val;
    }
    red_s[tid] = pp;
    __syncthreads();
    float ms  = (red_s[r * 4 + 0] + red_s[r * 4 + 1] + red_s[r * 4 + 2] + red_s[r * 4 + 3]) * (1.f / 128.f);
    float rms = rsqrtf(ms + 1e-5f);
    #pragma unroll 8
    for (int e = mq * 32; e < mq * 32 + 32; e++) {
        g_o[(size_t)(row0 + r) * DD + col0 + e] = o_s[r * QS + e] * dinv * rms * g_w[e];
    }
}

// ============================================================================
// launch
// ============================================================================
extern "C" void kernel_launch(void* const* d_in, const int* in_sizes, int n_in,
                              void* d_out, int out_size)
{
    const float* x    = (const float*)d_in[0];
    const float* Wq   = (const float*)d_in[1];
    const float* Wk   = (const float*)d_in[2];
    const float* Wv   = (const float*)d_in[3];
    const float* Wo   = (const float*)d_in[4];
    const float* fq1w = (const float*)d_in[5];
    const float* fq1b = (const float*)d_in[6];
    const float* fq2w = (const float*)d_in[7];
    const float* fq2b = (const float*)d_in[8];
    const float* fk1w = (const float*)d_in[9];
    const float* fk1b = (const float*)d_in[10];
    const float* fk2w = (const float*)d_in[11];
    const float* fk2b = (const float*)d_in[12];
    const float* gw   = (const float*)d_in[13];
    float* out = (float*)d_out;

    cudaFuncSetAttribute(featmap_kernel,  cudaFuncAttributeMaxDynamicSharedMemorySize, 163840);
    cudaFuncSetAttribute(chunk_kv_kernel, cudaFuncAttributeMaxDynamicSharedMemorySize, 65536);
    cudaFuncSetAttribute(chunk_out_kernel, cudaFuncAttributeMaxDynamicSharedMemorySize, 188160);

    float *q_p, *k_p, *v_p, *fq_p, *fk_p, *o_p;
    cudaGetSymbolAddress((void**)&q_p,  g_q);
    cudaGetSymbolAddress((void**)&k_p,  g_k);
    cudaGetSymbolAddress((void**)&v_p,  g_v);
    cudaGetSymbolAddress((void**)&fq_p, g_fq);
    cudaGetSymbolAddress((void**)&fk_p, g_fk);
    cudaGetSymbolAddress((void**)&o_p,  g_o);

    dim3 gemm_grid(DD / 128, TTOT / 128);   // (8, 128)

    sgemm_kernel<<<gemm_grid, 256>>>(x, Wq, q_p, TTOT, DD, DD);
    sgemm_kernel<<<gemm_grid, 256>>>(x, Wk, k_p, TTOT, DD, DD);
    sgemm_kernel<<<gemm_grid, 256>>>(x, Wv, v_p, TTOT, DD, DD);

    featmap_kernel<<<dim3(TTOT / 64, HH), 512, 163840>>>(
        q_p, fq1w, fq1b, fq2w, fq2b, fq_p, 0.08838834764831845f /* 128^-0.5 */);
    featmap_kernel<<<dim3(TTOT / 64, HH), 512, 163840>>>(
        k_p, fk1w, fk1b, fk2w, fk2b, fk_p, 1.0f);

    chunk_kv_kernel<<<dim3(NCH, BHN), 256, 65536>>>();
    scan_kernel<<<dim3(64, BHN), 256>>>();
    chunk_out_kernel<<<dim3(NCH, BHN), 256, 188160>>>(gw);

    sgemm_kernel<<<gemm_grid, 256>>>(o_p, Wo, out, TTOT, DD, DD);
}

// round 5
// speedup vs baseline: 1.9001x; 1.9001x over previous
#include <cuda_runtime.h>
#include <cuda_bf16.h>
#include <cstdint>

// Problem constants
#define BB      2
#define TT      8192
#define DD      1024
#define HH      8
#define DK      128
#define DV      128
#define CH      64
#define NCH     128
#define BHN     16
#define TTOT    16384
#define NCHUNKS 2048

// -------- scratch (device globals; no allocation allowed) --------
__device__ float g_q [TTOT * DD];
__device__ float g_k [TTOT * DD];
__device__ float g_v [TTOT * DD];
__device__ float g_fq[TTOT * DD];
__device__ float g_fk[TTOT * DD];
__device__ float g_o [TTOT * DD];
__device__ float g_S [(size_t)NCHUNKS * DK * DV];
__device__ float g_Z [(size_t)NCHUNKS * DK];
__device__ __nv_bfloat16 g_ahi[(size_t)TTOT * DD];
__device__ __nv_bfloat16 g_alo[(size_t)TTOT * DD];
__device__ __nv_bfloat16 g_wthi[4ull * DD * DD];
__device__ __nv_bfloat16 g_wtlo[4ull * DD * DD];

// ============================================================================
// PTX helpers (sm_80+ only: cp.async, ldmatrix, mma.sync — assemble on sm_100)
// ============================================================================
__device__ __forceinline__ uint32_t smem_u32(const void* p) {
    uint32_t a;
    asm("{ .reg .u64 t; cvta.to.shared.u64 t, %1; cvt.u32.u64 %0, t; }" : "=r"(a) : "l"(p));
    return a;
}
#define CP_ASYNC16(dst_u32, src_ptr) \
    asm volatile("cp.async.cg.shared.global [%0], [%1], 16;" :: "r"(dst_u32), "l"(src_ptr) : "memory")
#define CP_COMMIT() asm volatile("cp.async.commit_group;" ::: "memory")
#define CP_WAIT(n)  asm volatile("cp.async.wait_group %0;" :: "n"(n) : "memory")

#define LDSM_X4(r0, r1, r2, r3, addr) \
    asm volatile("ldmatrix.sync.aligned.m8n8.x4.shared.b16 {%0,%1,%2,%3}, [%4];" \
        : "=r"(r0), "=r"(r1), "=r"(r2), "=r"(r3) : "r"(addr))

#define MMA16816(c, a, b) \
    asm volatile("mma.sync.aligned.m16n8k16.row.col.f32.bf16.bf16.f32 " \
        "{%0,%1,%2,%3}, {%4,%5,%6,%7}, {%8,%9}, {%0,%1,%2,%3};" \
        : "+f"((c)[0]), "+f"((c)[1]), "+f"((c)[2]), "+f"((c)[3]) \
        : "r"((a)[0]), "r"((a)[1]), "r"((a)[2]), "r"((a)[3]), "r"((b)[0]), "r"((b)[1]))

// ============================================================================
// split kernels: fp32 -> (hi, lo) bf16 pair;  and transpose-split for weights
// ============================================================================
__global__ void __launch_bounds__(256) split_kernel(
    const float* __restrict__ in, __nv_bfloat16* __restrict__ hi, __nv_bfloat16* __restrict__ lo)
{
    size_t idx = ((size_t)blockIdx.x * 256 + threadIdx.x) * 8;
    float4 a = *(const float4*)&in[idx];
    float4 b = *(const float4*)&in[idx + 4];
    float v[8] = {a.x, a.y, a.z, a.w, b.x, b.y, b.z, b.w};
    __nv_bfloat16 h[8], l[8];
    #pragma unroll
    for (int t = 0; t < 8; t++) {
        h[t] = __float2bfloat16(v[t]);
        l[t] = __float2bfloat16(v[t] - __bfloat162float(h[t]));
    }
    *(uint4*)&hi[idx] = *(uint4*)h;
    *(uint4*)&lo[idx] = *(uint4*)l;
}

__global__ void transpose_split_kernel(
    const float* __restrict__ W, __nv_bfloat16* __restrict__ hi, __nv_bfloat16* __restrict__ lo)
{
    __shared__ float ts[32][33];
    int tx = threadIdx.x, ty = threadIdx.y;
    int n0 = blockIdx.x * 32, k0 = blockIdx.y * 32;
    for (int i = ty; i < 32; i += 8) ts[i][tx] = W[(size_t)(k0 + i) * DD + n0 + tx];
    __syncthreads();
    for (int i = ty; i < 32; i += 8) {
        float v = ts[tx][i];                 // W[k0+tx][n0+i]
        __nv_bfloat16 h = __float2bfloat16(v);
        __nv_bfloat16 l = __float2bfloat16(v - __bfloat162float(h));
        size_t o = (size_t)(n0 + i) * DD + k0 + tx;
        hi[o] = h; lo[o] = l;
    }
}

// ============================================================================
// mma.sync bf16 GEMM with 2-term split: C = Ahi*Bhi + Ahi*Blo + Alo*Bhi.
// A: [M,1024] row-major (k contig). B: [1024(n),1024(k)] (k contig) = W^T.
// CTA tile 128x128, BK=32, 8 warps of 64x32, 3-stage cp.async pipeline.
// SMEM row layout per stage: 128 rows x 128B  [hi 64B | lo 64B], XOR-16B swizzle.
// ============================================================================
#define MG_STAGE 32768
#define MG_B_OFF 16384
#define MG_SMEM  (3 * MG_STAGE)   // 98304

__device__ __forceinline__ void mg_load_stage(
    uint32_t stb, int tid, int kt, int rowBase, int colBase,
    const __nv_bfloat16* __restrict__ Ahi, const __nv_bfloat16* __restrict__ Alo,
    const __nv_bfloat16* __restrict__ Bhi, const __nv_bfloat16* __restrict__ Blo)
{
    #pragma unroll
    for (int j = 0; j < 8; j++) {
        int l = tid + j * 256;          // 0..2047
        int isB = l >> 10;
        int ll = l & 1023;
        int r = ll >> 3, c = ll & 7;    // row 0..127, 16B-chunk 0..7 (0-3 hi, 4-7 lo)
        const __nv_bfloat16* g;
        int gr;
        if (!isB) { g = (c < 4) ? Ahi : Alo; gr = rowBase + r; }
        else      { g = (c < 4) ? Bhi : Blo; gr = colBase + r; }
        const void* src = g + (size_t)gr * DD + kt + (c & 3) * 8;
        uint32_t off = (uint32_t)(r * 128) + (((uint32_t)c * 16) ^ (((uint32_t)(r & 7)) << 4));
        CP_ASYNC16(stb + isB * MG_B_OFF + off, src);
    }
}

__global__ void __launch_bounds__(256, 2) mma_gemm_kernel(
    const __nv_bfloat16* __restrict__ Ahi, const __nv_bfloat16* __restrict__ Alo,
    const __nv_bfloat16* __restrict__ Bhi, const __nv_bfloat16* __restrict__ Blo,
    float* __restrict__ C)
{
    extern __shared__ __align__(1024) char smem[];
    uint32_t sb = smem_u32(smem);
    const int tid  = threadIdx.x;
    const int wid  = tid >> 5;
    const int lane = tid & 31;
    const int warp_m = wid >> 2;       // 0..1
    const int warp_n = wid & 3;        // 0..3
    const int rowBase = blockIdx.y * 128;
    const int colBase = blockIdx.x * 128;

    // prologue: stages 0, 1
    mg_load_stage(sb + 0 * MG_STAGE, tid, 0,  rowBase, colBase, Ahi, Alo, Bhi, Blo);
    CP_COMMIT();
    mg_load_stage(sb + 1 * MG_STAGE, tid, 32, rowBase, colBase, Ahi, Alo, Bhi, Blo);
    CP_COMMIT();

    float acc[4][4][4];
    #pragma unroll
    for (int mi = 0; mi < 4; mi++)
        #pragma unroll
        for (int ni = 0; ni < 4; ni++)
            #pragma unroll
            for (int t = 0; t < 4; t++) acc[mi][ni][t] = 0.f;

    // ldmatrix lane geometry
    const int aRow  = warp_m * 64 + (lane & 7) + ((lane >> 3) & 1) * 8;  // + mi*16
    const uint32_t aKB = ((lane >> 4) & 1) * 16;                          // 16B chunk within k16
    const int bRow  = warp_n * 32 + (lane & 7) + ((lane >> 4) & 1) * 8;  // + ni2*16
    const uint32_t bKB = ((lane >> 3) & 1) * 16;

    for (int ci = 0; ci < 32; ci++) {
        CP_WAIT(1);
        __syncthreads();
        if (ci + 2 < 32)
            mg_load_stage(sb + ((ci + 2) % 3) * MG_STAGE, tid, (ci + 2) * 32,
                          rowBase, colBase, Ahi, Alo, Bhi, Blo);
        CP_COMMIT();

        uint32_t stb = sb + (ci % 3) * MG_STAGE;
        #pragma unroll
        for (int j = 0; j < 2; j++) {
            // B fragments (hi & lo), 4 n8k16 frags each
            uint32_t bh[4][2], bl[4][2];
            #pragma unroll
            for (int ni2 = 0; ni2 < 2; ni2++) {
                int nr = bRow + ni2 * 16;
                uint32_t rbase = stb + MG_B_OFF + nr * 128;
                uint32_t swz = ((uint32_t)(nr & 7)) << 4;
                uint32_t koff = j * 32 + bKB;
                LDSM_X4(bh[ni2 * 2][0], bh[ni2 * 2][1], bh[ni2 * 2 + 1][0], bh[ni2 * 2 + 1][1],
                        rbase + (koff ^ swz));
                LDSM_X4(bl[ni2 * 2][0], bl[ni2 * 2][1], bl[ni2 * 2 + 1][0], bl[ni2 * 2 + 1][1],
                        rbase + ((koff + 64) ^ swz));
            }
            #pragma unroll
            for (int mi = 0; mi < 4; mi++) {
                int ar = aRow + mi * 16;
                uint32_t rbase = stb + ar * 128;
                uint32_t swz = ((uint32_t)(ar & 7)) << 4;
                uint32_t koff = j * 32 + aKB;
                uint32_t ah[4], al[4];
                LDSM_X4(ah[0], ah[1], ah[2], ah[3], rbase + (koff ^ swz));
                LDSM_X4(al[0], al[1], al[2], al[3], rbase + ((koff + 64) ^ swz));
                #pragma unroll
                for (int ni = 0; ni < 4; ni++) {
                    MMA16816(acc[mi][ni], ah, bh[ni]);
                    MMA16816(acc[mi][ni], ah, bl[ni]);
                    MMA16816(acc[mi][ni], al, bh[ni]);
                }
            }
        }
    }

    // epilogue: accumulator fragment -> global
    #pragma unroll
    for (int mi = 0; mi < 4; mi++) {
        int r0 = rowBase + warp_m * 64 + mi * 16 + (lane >> 2);
        #pragma unroll
        for (int ni = 0; ni < 4; ni++) {
            int c0 = colBase + warp_n * 32 + ni * 8 + (lane & 3) * 2;
            *(float2*)&C[(size_t)r0 * DD + c0]       = make_float2(acc[mi][ni][0], acc[mi][ni][1]);
            *(float2*)&C[(size_t)(r0 + 8) * DD + c0] = make_float2(acc[mi][ni][2], acc[mi][ni][3]);
        }
    }
}

// ============================================================================
// Feature map: out = (in@W1 + b1) * (in@W2 + b2) * scale, per head.
// ============================================================================
__global__ void __launch_bounds__(512) featmap_kernel(
    const float* __restrict__ in,
    const float* __restrict__ W1, const float* __restrict__ b1,
    const float* __restrict__ W2, const float* __restrict__ b2,
    float* __restrict__ out, float scale)
{
    extern __shared__ float sm[];
    float* x_s  = sm;
    float* w1_s = sm + 8192;
    float* w2_s = sm + 24576;

    const int tid  = threadIdx.x;
    const int row0 = blockIdx.x * 64;
    const int h    = blockIdx.y;
    const size_t base = (size_t)row0 * DD + h * DK;

    #pragma unroll
    for (int i = 0; i < 4; i++) {
        int lin = tid + i * 512;
        int rr = lin >> 5;
        int c  = (lin & 31) << 2;
        *(float4*)&x_s[rr * 128 + c] = *(const float4*)&in[base + (size_t)rr * DD + c];
    }
    #pragma unroll
    for (int i = 0; i < 8; i++) {
        int lin = tid + i * 512;
        int rr = lin >> 5;
        int c  = (lin & 31) << 2;
        *(float4*)&w1_s[rr * 128 + c] = *(const float4*)&W1[rr * 128 + c];
        *(float4*)&w2_s[rr * 128 + c] = *(const float4*)&W2[rr * 128 + c];
    }
    __syncthreads();

    const int c0 = (tid & 31) * 4;
    const int r0 = (tid >> 5) * 4;

    float a1[4][4], a2[4][4];
    #pragma unroll
    for (int i = 0; i < 4; i++)
        #pragma unroll
        for (int j = 0; j < 4; j++) { a1[i][j] = 0.f; a2[i][j] = 0.f; }

    for (int k = 0; k < 128; k++) {
        float4 w1 = *(float4*)&w1_s[k * 128 + c0];
        float4 w2 = *(float4*)&w2_s[k * 128 + c0];
        #pragma unroll
        for (int i = 0; i < 4; i++) {
            float xv = x_s[(r0 + i) * 128 + k];
            a1[i][0] = fmaf(xv, w1.x, a1[i][0]);
            a1[i][1] = fmaf(xv, w1.y, a1[i][1]);
            a1[i][2] = fmaf(xv, w1.z, a1[i][2]);
            a1[i][3] = fmaf(xv, w1.w, a1[i][3]);
            a2[i][0] = fmaf(xv, w2.x, a2[i][0]);
            a2[i][1] = fmaf(xv, w2.y, a2[i][1]);
            a2[i][2] = fmaf(xv, w2.z, a2[i][2]);
            a2[i][3] = fmaf(xv, w2.w, a2[i][3]);
        }
    }

    float4 bb1 = *(const float4*)&b1[c0];
    float4 bb2 = *(const float4*)&b2[c0];
    #pragma unroll
    for (int i = 0; i < 4; i++) {
        float4 o;
        o.x = (a1[i][0] + bb1.x) * (a2[i][0] + bb2.x) * scale;
        o.y = (a1[i][1] + bb1.y) * (a2[i][1] + bb2.y) * scale;
        o.z = (a1[i][2] + bb1.z) * (a2[i][2] + bb2.z) * scale;
        o.w = (a1[i][3] + bb1.w) * (a2[i][3] + bb2.w) * scale;
        *(float4*)&out[base + (size_t)(r0 + i) * DD + c0] = o;
    }
}

// ============================================================================
// Per-chunk kv = fk^T @ v and ksum.
// ============================================================================
__global__ void __launch_bounds__(256) chunk_kv_kernel()
{
    extern __shared__ float sm[];
    float* k_s = sm;
    float* v_s = sm + 8192;

    const int tid = threadIdx.x;
    const int n  = blockIdx.x;
    const int bh = blockIdx.y;
    const int b  = bh >> 3, h = bh & 7;
    const int row0 = b * TT + n * CH;
    const int col0 = h * DK;

    #pragma unroll
    for (int i = 0; i < 8; i++) {
        int lin = tid + i * 256;
        int r = lin >> 5;
        int c = (lin & 31) << 2;
        size_t src = (size_t)(row0 + r) * DD + col0 + c;
        *(float4*)&k_s[r * 128 + c] = *(const float4*)&g_fk[src];
        *(float4*)&v_s[r * 128 + c] = *(const float4*)&g_v[src];
    }
    __syncthreads();

    const int d0 = (tid >> 4) * 8;
    const int e0 = (tid & 15) * 8;
    float acc[8][8];
    #pragma unroll
    for (int i = 0; i < 8; i++)
        #pragma unroll
        for (int j = 0; j < 8; j++) acc[i][j] = 0.f;

    for (int t = 0; t < 64; t++) {
        float4 ka = *(float4*)&k_s[t * 128 + d0];
        float4 kb = *(float4*)&k_s[t * 128 + d0 + 4];
        float4 va = *(float4*)&v_s[t * 128 + e0];
        float4 vb = *(float4*)&v_s[t * 128 + e0 + 4];
        float kk[8] = {ka.x, ka.y, ka.z, ka.w, kb.x, kb.y, kb.z, kb.w};
        float vv[8] = {va.x, va.y, va.z, va.w, vb.x, vb.y, vb.z, vb.w};
        #pragma unroll
        for (int i = 0; i < 8; i++)
            #pragma unroll
            for (int j = 0; j < 8; j++)
                acc[i][j] = fmaf(kk[i], vv[j], acc[i][j]);
    }

    size_t sb = ((size_t)bh * NCH + n) * (DK * DV);
    #pragma unroll
    for (int i = 0; i < 8; i++) {
        *(float4*)&g_S[sb + (size_t)(d0 + i) * DV + e0]     = make_float4(acc[i][0], acc[i][1], acc[i][2], acc[i][3]);
        *(float4*)&g_S[sb + (size_t)(d0 + i) * DV + e0 + 4] = make_float4(acc[i][4], acc[i][5], acc[i][6], acc[i][7]);
    }

    if (tid < 128) {
        float s = 0.f;
        for (int t = 0; t < 64; t++) s += k_s[t * 128 + tid];
        g_Z[((size_t)bh * NCH + n) * DK + tid] = s;
    }
}

// ============================================================================
// Exclusive prefix scan over chunks.
// ============================================================================
__global__ void __launch_bounds__(256) scan_kernel()
{
    const int bh  = blockIdx.y;
    const int idx = blockIdx.x * 256 + threadIdx.x;

    float run = 0.f;
    size_t base = (size_t)bh * NCH * (DK * DV) + idx;
    for (int n = 0; n < NCH; n++) {
        size_t a = base + (size_t)n * (DK * DV);
        float t = g_S[a];
        g_S[a] = run;
        run += t;
    }
    if (blockIdx.x == 0 && threadIdx.x < DK) {
        float rz = 0.f;
        size_t zb = (size_t)bh * NCH * DK + threadIdx.x;
        for (int n = 0; n < NCH; n++) {
            size_t a = zb + (size_t)n * DK;
            float t = g_Z[a];
            g_Z[a] = rz;
            rz += t;
        }
    }
}

// ============================================================================
// Per-chunk output.
// ============================================================================
#define QS 132
#define AS 65

__global__ void __launch_bounds__(256) chunk_out_kernel(const float* __restrict__ g_w)
{
    extern __shared__ float sm[];
    float* q_s    = sm;
    float* k_s    = sm + 8448;
    float* v_s    = sm + 16896;
    float* S_s    = sm + 25344;
    float* attn_s = sm + 42240;
    float* Z_s    = sm + 46400;
    float* den_s  = sm + 46528;
    float* red_s  = sm + 46784;

    const int tid = threadIdx.x;
    const int n  = blockIdx.x;
    const int bh = blockIdx.y;
    const int b  = bh >> 3, h = bh & 7;
    const int row0 = b * TT + n * CH;
    const int col0 = h * DK;

    #pragma unroll
    for (int i = 0; i < 8; i++) {
        int lin = tid + i * 256;
        int r = lin >> 5;
        int c = (lin & 31) << 2;
        size_t src = (size_t)(row0 + r) * DD + col0 + c;
        *(float4*)&q_s[r * QS + c] = *(const float4*)&g_fq[src];
        *(float4*)&k_s[r * QS + c] = *(const float4*)&g_fk[src];
        *(float4*)&v_s[r * QS + c] = *(const float4*)&g_v[src];
    }
    size_t sbase = ((size_t)bh * NCH + n) * (DK * DV);
    #pragma unroll
    for (int i = 0; i < 16; i++) {
        int lin = tid + i * 256;
        int d = lin >> 5;
        int c = (lin & 31) << 2;
        *(float4*)&S_s[d * QS + c] = *(const float4*)&g_S[sbase + (size_t)d * DV + c];
    }
    if (tid < 32)
        *(float4*)&Z_s[tid * 4] = *(const float4*)&g_Z[((size_t)bh * NCH + n) * DK + tid * 4];
    __syncthreads();

    const int r  = tid >> 2;
    const int mq = tid & 3;
    {
        float denp = 0.f;
        for (int mm = 0; mm < 16; mm++) {
            int m = mq * 16 + mm;
            float a = 0.f;
            if (m <= r) {
                #pragma unroll 8
                for (int d4 = 0; d4 < 32; d4++) {
                    float4 qv = *(float4*)&q_s[r * QS + d4 * 4];
                    float4 kv = *(float4*)&k_s[m * QS + d4 * 4];
                    a += qv.x * kv.x + qv.y * kv.y + qv.z * kv.z + qv.w * kv.w;
                }
                denp += a;
            }
            attn_s[r * AS + m] = (m <= r) ? a : 0.f;
        }
        #pragma unroll 8
        for (int d = mq * 32; d < mq * 32 + 32; d++)
            denp += q_s[r * QS + d] * Z_s[d];
        den_s[tid] = denp;
    }
    __syncthreads();

    const int ty = tid >> 4;
    const int tx = tid & 15;
    const int e0 = tx * 8;
    float acc[4][8];
    #pragma unroll
    for (int i = 0; i < 4; i++)
        #pragma unroll
        for (int j = 0; j < 8; j++) acc[i][j] = 0.f;

    for (int m = 0; m < 64; m++) {
        float4 va = *(float4*)&v_s[m * QS + e0];
        float4 vb = *(float4*)&v_s[m * QS + e0 + 4];
        #pragma unroll
        for (int i = 0; i < 4; i++) {
            float a = attn_s[(ty * 4 + i) * AS + m];
            acc[i][0] = fmaf(a, va.x, acc[i][0]);
            acc[i][1] = fmaf(a, va.y, acc[i][1]);
            acc[i][2] = fmaf(a, va.z, acc[i][2]);
            acc[i][3] = fmaf(a, va.w, acc[i][3]);
            acc[i][4] = fmaf(a, vb.x, acc[i][4]);
            acc[i][5] = fmaf(a, vb.y, acc[i][5]);
            acc[i][6] = fmaf(a, vb.z, acc[i][6]);
            acc[i][7] = fmaf(a, vb.w, acc[i][7]);
        }
    }
    for (int d = 0; d < 128; d++) {
        float4 sa = *(float4*)&S_s[d * QS + e0];
        float4 sb2 = *(float4*)&S_s[d * QS + e0 + 4];
        #pragma unroll
        for (int i = 0; i < 4; i++) {
            float qv = q_s[(ty * 4 + i) * QS + d];
            acc[i][0] = fmaf(qv, sa.x, acc[i][0]);
            acc[i][1] = fmaf(qv, sa.y, acc[i][1]);
            acc[i][2] = fmaf(qv, sa.z, acc[i][2]);
            acc[i][3] = fmaf(qv, sa.w, acc[i][3]);
            acc[i][4] = fmaf(qv, sb2.x, acc[i][4]);
            acc[i][5] = fmaf(qv, sb2.y, acc[i][5]);
            acc[i][6] = fmaf(qv, sb2.z, acc[i][6]);
            acc[i][7] = fmaf(qv, sb2.w, acc[i][7]);
        }
    }
    float* o_s = k_s;
    #pragma unroll
    for (int i = 0; i < 4; i++) {
        *(float4*)&o_s[(ty * 4 + i) * QS + e0]     = make_float4(acc[i][0], acc[i][1], acc[i][2], acc[i][3]);
        *(float4*)&o_s[(ty * 4 + i) * QS + e0 + 4] = make_float4(acc[i][4], acc[i][5], acc[i][6], acc[i][7]);
    }
    __syncthreads();

    float den = den_s[r * 4 + 0] + den_s[r * 4 + 1] + den_s[r * 4 + 2] + den_s[r * 4 + 3];
    float dinv = 1.f / (den + 1e-6f);
    float pp = 0.f;
    #pragma unroll 8
    for (int e = mq * 32; e < mq * 32 + 32; e++) {
        float val = o_s[r * QS + e] * dinv;
        pp += val * val;
    }
    red_s[tid] = pp;
    __syncthreads();
    float ms  = (red_s[r * 4 + 0] + red_s[r * 4 + 1] + red_s[r * 4 + 2] + red_s[r * 4 + 3]) * (1.f / 128.f);
    float rms = rsqrtf(ms + 1e-5f);
    #pragma unroll 8
    for (int e = mq * 32; e < mq * 32 + 32; e++) {
        g_o[(size_t)(row0 + r) * DD + col0 + e] = o_s[r * QS + e] * dinv * rms * g_w[e];
    }
}

// ============================================================================
// launch
// ============================================================================
extern "C" void kernel_launch(void* const* d_in, const int* in_sizes, int n_in,
                              void* d_out, int out_size)
{
    const float* x    = (const float*)d_in[0];
    const float* Wq   = (const float*)d_in[1];
    const float* Wk   = (const float*)d_in[2];
    const float* Wv   = (const float*)d_in[3];
    const float* Wo   = (const float*)d_in[4];
    const float* fq1w = (const float*)d_in[5];
    const float* fq1b = (const float*)d_in[6];
    const float* fq2w = (const float*)d_in[7];
    const float* fq2b = (const float*)d_in[8];
    const float* fk1w = (const float*)d_in[9];
    const float* fk1b = (const float*)d_in[10];
    const float* fk2w = (const float*)d_in[11];
    const float* fk2b = (const float*)d_in[12];
    const float* gw   = (const float*)d_in[13];
    float* out = (float*)d_out;

    cudaFuncSetAttribute(featmap_kernel,   cudaFuncAttributeMaxDynamicSharedMemorySize, 163840);
    cudaFuncSetAttribute(chunk_kv_kernel,  cudaFuncAttributeMaxDynamicSharedMemorySize, 65536);
    cudaFuncSetAttribute(chunk_out_kernel, cudaFuncAttributeMaxDynamicSharedMemorySize, 188160);
    cudaFuncSetAttribute(mma_gemm_kernel,  cudaFuncAttributeMaxDynamicSharedMemorySize, MG_SMEM);

    float *q_p, *k_p, *v_p, *fq_p, *fk_p, *o_p;
    __nv_bfloat16 *ahi_p, *alo_p, *wthi_p, *wtlo_p;
    cudaGetSymbolAddress((void**)&q_p,  g_q);
    cudaGetSymbolAddress((void**)&k_p,  g_k);
    cudaGetSymbolAddress((void**)&v_p,  g_v);
    cudaGetSymbolAddress((void**)&fq_p, g_fq);
    cudaGetSymbolAddress((void**)&fk_p, g_fk);
    cudaGetSymbolAddress((void**)&o_p,  g_o);
    cudaGetSymbolAddress((void**)&ahi_p, g_ahi);
    cudaGetSymbolAddress((void**)&alo_p, g_alo);
    cudaGetSymbolAddress((void**)&wthi_p, g_wthi);
    cudaGetSymbolAddress((void**)&wtlo_p, g_wtlo);

    const size_t WSZ = (size_t)DD * DD;
    dim3 tblk(32, 8), tgrd(32, 32);
    transpose_split_kernel<<<tgrd, tblk>>>(Wq, wthi_p + 0 * WSZ, wtlo_p + 0 * WSZ);
    transpose_split_kernel<<<tgrd, tblk>>>(Wk, wthi_p + 1 * WSZ, wtlo_p + 1 * WSZ);
    transpose_split_kernel<<<tgrd, tblk>>>(Wv, wthi_p + 2 * WSZ, wtlo_p + 2 * WSZ);
    transpose_split_kernel<<<tgrd, tblk>>>(Wo, wthi_p + 3 * WSZ, wtlo_p + 3 * WSZ);

    split_kernel<<<8192, 256>>>(x, ahi_p, alo_p);

    dim3 ggrid(DD / 128, TTOT / 128);  // (8, 128)
    mma_gemm_kernel<<<ggrid, 256, MG_SMEM>>>(ahi_p, alo_p, wthi_p + 0 * WSZ, wtlo_p + 0 * WSZ, q_p);
    mma_gemm_kernel<<<ggrid, 256, MG_SMEM>>>(ahi_p, alo_p, wthi_p + 1 * WSZ, wtlo_p + 1 * WSZ, k_p);
    mma_gemm_kernel<<<ggrid, 256, MG_SMEM>>>(ahi_p, alo_p, wthi_p + 2 * WSZ, wtlo_p + 2 * WSZ, v_p);

    featmap_kernel<<<dim3(TTOT / 64, HH), 512, 163840>>>(
        q_p, fq1w, fq1b, fq2w, fq2b, fq_p, 0.08838834764831845f);
    featmap_kernel<<<dim3(TTOT / 64, HH), 512, 163840>>>(
        k_p, fk1w, fk1b, fk2w, fk2b, fk_p, 1.0f);

    chunk_kv_kernel<<<dim3(NCH, BHN), 256, 65536>>>();
    scan_kernel<<<dim3(64, BHN), 256>>>();
    chunk_out_kernel<<<dim3(NCH, BHN), 256, 188160>>>(gw);

    split_kernel<<<8192, 256>>>(o_p, ahi_p, alo_p);
    mma_gemm_kernel<<<ggrid, 256, MG_SMEM>>>(ahi_p, alo_p, wthi_p + 3 * WSZ, wtlo_p + 3 * WSZ, out);
}

// round 6
// speedup vs baseline: 2.1258x; 1.1188x over previous
#include <cuda_runtime.h>
#include <cuda_bf16.h>
#include <cstdint>

// Problem constants
#define BB      2
#define TT      8192
#define DD      1024
#define HH      8
#define DK      128
#define DV      128
#define CH      64
#define NCH     128
#define BHN     16
#define TTOT    16384
#define NCHUNKS 2048

// -------- scratch (device globals; no allocation allowed) --------
__device__ float g_q [TTOT * DD];
__device__ float g_k [TTOT * DD];
__device__ float g_v [TTOT * DD];
__device__ float g_fq[TTOT * DD];
__device__ float g_fk[TTOT * DD];
__device__ float g_o [TTOT * DD];
__device__ float g_S [(size_t)NCHUNKS * DK * DV];
__device__ float g_Z [(size_t)NCHUNKS * DK];
__device__ __nv_bfloat16 g_ahi[(size_t)TTOT * DD];
__device__ __nv_bfloat16 g_alo[(size_t)TTOT * DD];
__device__ __nv_bfloat16 g_wthi[4ull * DD * DD];
__device__ __nv_bfloat16 g_wtlo[4ull * DD * DD];
// feature-map weights, transposed ([n][k]) + split: order q1,q2,k1,k2
__device__ __nv_bfloat16 g_fwhi[4 * DK * DK];
__device__ __nv_bfloat16 g_fwlo[4 * DK * DK];

// ============================================================================
// PTX helpers (sm_80+ only: cp.async, ldmatrix, mma.sync — assemble on sm_100)
// ============================================================================
__device__ __forceinline__ uint32_t smem_u32(const void* p) {
    uint32_t a;
    asm("{ .reg .u64 t; cvta.to.shared.u64 t, %1; cvt.u32.u64 %0, t; }" : "=r"(a) : "l"(p));
    return a;
}
#define CP_ASYNC16(dst_u32, src_ptr) \
    asm volatile("cp.async.cg.shared.global [%0], [%1], 16;" :: "r"(dst_u32), "l"(src_ptr) : "memory")
#define CP_COMMIT() asm volatile("cp.async.commit_group;" ::: "memory")
#define CP_WAIT(n)  asm volatile("cp.async.wait_group %0;" :: "n"(n) : "memory")

#define LDSM_X4(r0, r1, r2, r3, addr) \
    asm volatile("ldmatrix.sync.aligned.m8n8.x4.shared.b16 {%0,%1,%2,%3}, [%4];" \
        : "=r"(r0), "=r"(r1), "=r"(r2), "=r"(r3) : "r"(addr))

#define MMA16816(c, a, b) \
    asm volatile("mma.sync.aligned.m16n8k16.row.col.f32.bf16.bf16.f32 " \
        "{%0,%1,%2,%3}, {%4,%5,%6,%7}, {%8,%9}, {%0,%1,%2,%3};" \
        : "+f"((c)[0]), "+f"((c)[1]), "+f"((c)[2]), "+f"((c)[3]) \
        : "r"((a)[0]), "r"((a)[1]), "r"((a)[2]), "r"((a)[3]), "r"((b)[0]), "r"((b)[1]))

__device__ __forceinline__ void split2(float2 v, uint32_t& h, uint32_t& l) {
    __nv_bfloat16 h0 = __float2bfloat16(v.x), h1 = __float2bfloat16(v.y);
    __nv_bfloat16 l0 = __float2bfloat16(v.x - __bfloat162float(h0));
    __nv_bfloat16 l1 = __float2bfloat16(v.y - __bfloat162float(h1));
    __nv_bfloat162 hh = __halves2bfloat162(h0, h1);
    __nv_bfloat162 ll = __halves2bfloat162(l0, l1);
    h = *reinterpret_cast<uint32_t*>(&hh);
    l = *reinterpret_cast<uint32_t*>(&ll);
}

// ============================================================================
// split kernels: fp32 -> (hi, lo) bf16 pair;  transpose-split for weights
// ============================================================================
__global__ void __launch_bounds__(256) split_kernel(
    const float* __restrict__ in, __nv_bfloat16* __restrict__ hi, __nv_bfloat16* __restrict__ lo)
{
    size_t idx = ((size_t)blockIdx.x * 256 + threadIdx.x) * 8;
    float4 a = *(const float4*)&in[idx];
    float4 b = *(const float4*)&in[idx + 4];
    float v[8] = {a.x, a.y, a.z, a.w, b.x, b.y, b.z, b.w};
    __nv_bfloat16 h[8], l[8];
    #pragma unroll
    for (int t = 0; t < 8; t++) {
        h[t] = __float2bfloat16(v[t]);
        l[t] = __float2bfloat16(v[t] - __bfloat162float(h[t]));
    }
    *(uint4*)&hi[idx] = *(uint4*)h;
    *(uint4*)&lo[idx] = *(uint4*)l;
}

__global__ void transpose_split_kernel(
    const float* __restrict__ W, __nv_bfloat16* __restrict__ hi, __nv_bfloat16* __restrict__ lo)
{
    __shared__ float ts[32][33];
    int tx = threadIdx.x, ty = threadIdx.y;
    int n0 = blockIdx.x * 32, k0 = blockIdx.y * 32;
    for (int i = ty; i < 32; i += 8) ts[i][tx] = W[(size_t)(k0 + i) * DD + n0 + tx];
    __syncthreads();
    for (int i = ty; i < 32; i += 8) {
        float v = ts[tx][i];                 // W[k0+tx][n0+i]
        __nv_bfloat16 h = __float2bfloat16(v);
        __nv_bfloat16 l = __float2bfloat16(v - __bfloat162float(h));
        size_t o = (size_t)(n0 + i) * DD + k0 + tx;
        hi[o] = h; lo[o] = l;
    }
}

// same but for 128x128 feature-map weights (ld = DK)
__global__ void transpose_split128_kernel(
    const float* __restrict__ W, __nv_bfloat16* __restrict__ hi, __nv_bfloat16* __restrict__ lo)
{
    __shared__ float ts[32][33];
    int tx = threadIdx.x, ty = threadIdx.y;
    int n0 = blockIdx.x * 32, k0 = blockIdx.y * 32;
    for (int i = ty; i < 32; i += 8) ts[i][tx] = W[(k0 + i) * DK + n0 + tx];
    __syncthreads();
    for (int i = ty; i < 32; i += 8) {
        float v = ts[tx][i];                 // W[k0+tx][n0+i]
        __nv_bfloat16 h = __float2bfloat16(v);
        __nv_bfloat16 l = __float2bfloat16(v - __bfloat162float(h));
        int o = (n0 + i) * DK + k0 + tx;
        hi[o] = h; lo[o] = l;
    }
}

// ============================================================================
// mma.sync bf16 GEMM with 2-term split: C = Ahi*Bhi + Ahi*Blo + Alo*Bhi.
// (unchanged from Round 5 — verified at rel_err 1.2e-5)
// ============================================================================
#define MG_STAGE 32768
#define MG_B_OFF 16384
#define MG_SMEM  (3 * MG_STAGE)   // 98304

__device__ __forceinline__ void mg_load_stage(
    uint32_t stb, int tid, int kt, int rowBase, int colBase,
    const __nv_bfloat16* __restrict__ Ahi, const __nv_bfloat16* __restrict__ Alo,
    const __nv_bfloat16* __restrict__ Bhi, const __nv_bfloat16* __restrict__ Blo)
{
    #pragma unroll
    for (int j = 0; j < 8; j++) {
        int l = tid + j * 256;          // 0..2047
        int isB = l >> 10;
        int ll = l & 1023;
        int r = ll >> 3, c = ll & 7;    // row 0..127, 16B-chunk 0..7 (0-3 hi, 4-7 lo)
        const __nv_bfloat16* g;
        int gr;
        if (!isB) { g = (c < 4) ? Ahi : Alo; gr = rowBase + r; }
        else      { g = (c < 4) ? Bhi : Blo; gr = colBase + r; }
        const void* src = g + (size_t)gr * DD + kt + (c & 3) * 8;
        uint32_t off = (uint32_t)(r * 128) + (((uint32_t)c * 16) ^ (((uint32_t)(r & 7)) << 4));
        CP_ASYNC16(stb + isB * MG_B_OFF + off, src);
    }
}

__global__ void __launch_bounds__(256, 2) mma_gemm_kernel(
    const __nv_bfloat16* __restrict__ Ahi, const __nv_bfloat16* __restrict__ Alo,
    const __nv_bfloat16* __restrict__ Bhi, const __nv_bfloat16* __restrict__ Blo,
    float* __restrict__ C)
{
    extern __shared__ __align__(1024) char smem[];
    uint32_t sb = smem_u32(smem);
    const int tid  = threadIdx.x;
    const int wid  = tid >> 5;
    const int lane = tid & 31;
    const int warp_m = wid >> 2;
    const int warp_n = wid & 3;
    const int rowBase = blockIdx.y * 128;
    const int colBase = blockIdx.x * 128;

    mg_load_stage(sb + 0 * MG_STAGE, tid, 0,  rowBase, colBase, Ahi, Alo, Bhi, Blo);
    CP_COMMIT();
    mg_load_stage(sb + 1 * MG_STAGE, tid, 32, rowBase, colBase, Ahi, Alo, Bhi, Blo);
    CP_COMMIT();

    float acc[4][4][4];
    #pragma unroll
    for (int mi = 0; mi < 4; mi++)
        #pragma unroll
        for (int ni = 0; ni < 4; ni++)
            #pragma unroll
            for (int t = 0; t < 4; t++) acc[mi][ni][t] = 0.f;

    const int aRow  = warp_m * 64 + (lane & 7) + ((lane >> 3) & 1) * 8;
    const uint32_t aKB = ((lane >> 4) & 1) * 16;
    const int bRow  = warp_n * 32 + (lane & 7) + ((lane >> 4) & 1) * 8;
    const uint32_t bKB = ((lane >> 3) & 1) * 16;

    for (int ci = 0; ci < 32; ci++) {
        CP_WAIT(1);
        __syncthreads();
        if (ci + 2 < 32)
            mg_load_stage(sb + ((ci + 2) % 3) * MG_STAGE, tid, (ci + 2) * 32,
                          rowBase, colBase, Ahi, Alo, Bhi, Blo);
        CP_COMMIT();

        uint32_t stb = sb + (ci % 3) * MG_STAGE;
        #pragma unroll
        for (int j = 0; j < 2; j++) {
            uint32_t bh[4][2], bl[4][2];
            #pragma unroll
            for (int ni2 = 0; ni2 < 2; ni2++) {
                int nr = bRow + ni2 * 16;
                uint32_t rbase = stb + MG_B_OFF + nr * 128;
                uint32_t swz = ((uint32_t)(nr & 7)) << 4;
                uint32_t koff = j * 32 + bKB;
                LDSM_X4(bh[ni2 * 2][0], bh[ni2 * 2][1], bh[ni2 * 2 + 1][0], bh[ni2 * 2 + 1][1],
                        rbase + (koff ^ swz));
                LDSM_X4(bl[ni2 * 2][0], bl[ni2 * 2][1], bl[ni2 * 2 + 1][0], bl[ni2 * 2 + 1][1],
                        rbase + ((koff + 64) ^ swz));
            }
            #pragma unroll
            for (int mi = 0; mi < 4; mi++) {
                int ar = aRow + mi * 16;
                uint32_t rbase = stb + ar * 128;
                uint32_t swz = ((uint32_t)(ar & 7)) << 4;
                uint32_t koff = j * 32 + aKB;
                uint32_t ah[4], al[4];
                LDSM_X4(ah[0], ah[1], ah[2], ah[3], rbase + (koff ^ swz));
                LDSM_X4(al[0], al[1], al[2], al[3], rbase + ((koff + 64) ^ swz));
                #pragma unroll
                for (int ni = 0; ni < 4; ni++) {
                    MMA16816(acc[mi][ni], ah, bh[ni]);
                    MMA16816(acc[mi][ni], ah, bl[ni]);
                    MMA16816(acc[mi][ni], al, bh[ni]);
                }
            }
        }
    }

    #pragma unroll
    for (int mi = 0; mi < 4; mi++) {
        int r0 = rowBase + warp_m * 64 + mi * 16 + (lane >> 2);
        #pragma unroll
        for (int ni = 0; ni < 4; ni++) {
            int c0 = colBase + warp_n * 32 + ni * 8 + (lane & 3) * 2;
            *(float2*)&C[(size_t)r0 * DD + c0]       = make_float2(acc[mi][ni][0], acc[mi][ni][1]);
            *(float2*)&C[(size_t)(r0 + 8) * DD + c0] = make_float2(acc[mi][ni][2], acc[mi][ni][3]);
        }
    }
}

// ============================================================================
// featmap via mma.sync: out = (in@W1 + b1) * (in@W2 + b2) * scale, per head.
// 3-term bf16 split; A staged fp32 once, split at fragment build.
// CTA = 128 rows x 1 head. 8 warps x 16 rows. W^T hi/lo staged in smem.
// ============================================================================
#define FM_AS   132                      // A fp32 row stride (floats)
#define FM_WSB  272                      // W row stride (bytes; 136 bf16)
#define FM_W1H  67584
#define FM_W1L  (FM_W1H + 34816)         // 102400
#define FM_W2H  (FM_W1L + 34816)         // 137216
#define FM_W2L  (FM_W2H + 34816)         // 172032
#define FM_SMEM (FM_W2L + 34816)         // 206848

__global__ void __launch_bounds__(256) featmap_mma_kernel(
    const float* __restrict__ in,
    const __nv_bfloat16* __restrict__ w1hi, const __nv_bfloat16* __restrict__ w1lo,
    const __nv_bfloat16* __restrict__ w2hi, const __nv_bfloat16* __restrict__ w2lo,
    const float* __restrict__ b1, const float* __restrict__ b2,
    float* __restrict__ out, float scale)
{
    extern __shared__ __align__(16) char smem[];
    float* A_s = (float*)smem;
    const int tid = threadIdx.x, wid = tid >> 5, lane = tid & 31;
    const int row0 = blockIdx.x * 128;
    const int h = blockIdx.y;
    const size_t base = (size_t)row0 * DD + h * DK;

    // stage A (128x128 fp32, stride 132)
    #pragma unroll
    for (int i = 0; i < 16; i++) {
        int lin = tid + i * 256;           // 0..4095 float4s
        int r = lin >> 5, c = (lin & 31) * 4;
        *(float4*)&A_s[r * FM_AS + c] = *(const float4*)&in[base + (size_t)r * DD + c];
    }
    // stage W^T hi/lo (each 128x128 bf16 -> stride 136 elements)
    #pragma unroll
    for (int i = 0; i < 8; i++) {
        int lin = tid + i * 256;           // 0..2047
        int r = lin >> 4, c8 = lin & 15;
        int gsrc = r * DK + c8 * 8;
        uint32_t doff = (uint32_t)r * FM_WSB + c8 * 16;
        *(uint4*)(smem + FM_W1H + doff) = *(const uint4*)&w1hi[gsrc];
        *(uint4*)(smem + FM_W1L + doff) = *(const uint4*)&w1lo[gsrc];
        *(uint4*)(smem + FM_W2H + doff) = *(const uint4*)&w2hi[gsrc];
        *(uint4*)(smem + FM_W2L + doff) = *(const uint4*)&w2lo[gsrc];
    }
    __syncthreads();

    const int m0 = wid * 16;
    float acc1[16][4], acc2[16][4];
    #pragma unroll
    for (int ni = 0; ni < 16; ni++)
        #pragma unroll
        for (int t = 0; t < 4; t++) { acc1[ni][t] = 0.f; acc2[ni][t] = 0.f; }

    const int ar  = m0 + (lane >> 2);
    const int akc = (lane & 3) * 2;
    const int bn  = lane >> 2;

    for (int kk = 0; kk < 8; kk++) {
        int k0 = kk * 16;
        uint32_t ah[4], al[4];
        split2(*(float2*)&A_s[ar * FM_AS + k0 + akc],           ah[0], al[0]);
        split2(*(float2*)&A_s[(ar + 8) * FM_AS + k0 + akc],     ah[1], al[1]);
        split2(*(float2*)&A_s[ar * FM_AS + k0 + 8 + akc],       ah[2], al[2]);
        split2(*(float2*)&A_s[(ar + 8) * FM_AS + k0 + 8 + akc], ah[3], al[3]);

        uint32_t kb = (uint32_t)(k0 + akc) * 2;   // byte offset along k
        #pragma unroll
        for (int ni = 0; ni < 16; ni++) {
            uint32_t roff = (uint32_t)(ni * 8 + bn) * FM_WSB + kb;
            uint32_t w1h[2], w1l[2], w2h[2], w2l[2];
            w1h[0] = *(uint32_t*)(smem + FM_W1H + roff);
            w1h[1] = *(uint32_t*)(smem + FM_W1H + roff + 16);
            w1l[0] = *(uint32_t*)(smem + FM_W1L + roff);
            w1l[1] = *(uint32_t*)(smem + FM_W1L + roff + 16);
            w2h[0] = *(uint32_t*)(smem + FM_W2H + roff);
            w2h[1] = *(uint32_t*)(smem + FM_W2H + roff + 16);
            w2l[0] = *(uint32_t*)(smem + FM_W2L + roff);
            w2l[1] = *(uint32_t*)(smem + FM_W2L + roff + 16);
            MMA16816(acc1[ni], ah, w1h);
            MMA16816(acc1[ni], ah, w1l);
            MMA16816(acc1[ni], al, w1h);
            MMA16816(acc2[ni], ah, w2h);
            MMA16816(acc2[ni], ah, w2l);
            MMA16816(acc2[ni], al, w2h);
        }
    }

    // epilogue: product + bias + scale
    const int orow = row0 + m0 + (lane >> 2);
    #pragma unroll
    for (int ni = 0; ni < 16; ni++) {
        int col = ni * 8 + (lane & 3) * 2;
        float2 bb1 = *(const float2*)&b1[col];
        float2 bb2 = *(const float2*)&b2[col];
        float o0 = (acc1[ni][0] + bb1.x) * (acc2[ni][0] + bb2.x) * scale;
        float o1 = (acc1[ni][1] + bb1.y) * (acc2[ni][1] + bb2.y) * scale;
        float o2 = (acc1[ni][2] + bb1.x) * (acc2[ni][2] + bb2.x) * scale;
        float o3 = (acc1[ni][3] + bb1.y) * (acc2[ni][3] + bb2.y) * scale;
        *(float2*)&out[(size_t)orow * DD + h * DK + col]       = make_float2(o0, o1);
        *(float2*)&out[(size_t)(orow + 8) * DD + h * DK + col] = make_float2(o2, o3);
    }
}

// ============================================================================
// Per-chunk kv = fk^T @ v and ksum.
// ============================================================================
__global__ void __launch_bounds__(256) chunk_kv_kernel()
{
    extern __shared__ float sm[];
    float* k_s = sm;
    float* v_s = sm + 8192;

    const int tid = threadIdx.x;
    const int n  = blockIdx.x;
    const int bh = blockIdx.y;
    const int b  = bh >> 3, h = bh & 7;
    const int row0 = b * TT + n * CH;
    const int col0 = h * DK;

    #pragma unroll
    for (int i = 0; i < 8; i++) {
        int lin = tid + i * 256;
        int r = lin >> 5;
        int c = (lin & 31) << 2;
        size_t src = (size_t)(row0 + r) * DD + col0 + c;
        *(float4*)&k_s[r * 128 + c] = *(const float4*)&g_fk[src];
        *(float4*)&v_s[r * 128 + c] = *(const float4*)&g_v[src];
    }
    __syncthreads();

    const int d0 = (tid >> 4) * 8;
    const int e0 = (tid & 15) * 8;
    float acc[8][8];
    #pragma unroll
    for (int i = 0; i < 8; i++)
        #pragma unroll
        for (int j = 0; j < 8; j++) acc[i][j] = 0.f;

    for (int t = 0; t < 64; t++) {
        float4 ka = *(float4*)&k_s[t * 128 + d0];
        float4 kb = *(float4*)&k_s[t * 128 + d0 + 4];
        float4 va = *(float4*)&v_s[t * 128 + e0];
        float4 vb = *(float4*)&v_s[t * 128 + e0 + 4];
        float kk[8] = {ka.x, ka.y, ka.z, ka.w, kb.x, kb.y, kb.z, kb.w};
        float vv[8] = {va.x, va.y, va.z, va.w, vb.x, vb.y, vb.z, vb.w};
        #pragma unroll
        for (int i = 0; i < 8; i++)
            #pragma unroll
            for (int j = 0; j < 8; j++)
                acc[i][j] = fmaf(kk[i], vv[j], acc[i][j]);
    }

    size_t sb = ((size_t)bh * NCH + n) * (DK * DV);
    #pragma unroll
    for (int i = 0; i < 8; i++) {
        *(float4*)&g_S[sb + (size_t)(d0 + i) * DV + e0]     = make_float4(acc[i][0], acc[i][1], acc[i][2], acc[i][3]);
        *(float4*)&g_S[sb + (size_t)(d0 + i) * DV + e0 + 4] = make_float4(acc[i][4], acc[i][5], acc[i][6], acc[i][7]);
    }

    if (tid < 128) {
        float s = 0.f;
        for (int t = 0; t < 64; t++) s += k_s[t * 128 + tid];
        g_Z[((size_t)bh * NCH + n) * DK + tid] = s;
    }
}

// ============================================================================
// Exclusive prefix scan over chunks.
// ============================================================================
__global__ void __launch_bounds__(256) scan_kernel()
{
    const int bh  = blockIdx.y;
    const int idx = blockIdx.x * 256 + threadIdx.x;

    float run = 0.f;
    size_t base = (size_t)bh * NCH * (DK * DV) + idx;
    for (int n = 0; n < NCH; n++) {
        size_t a = base + (size_t)n * (DK * DV);
        float t = g_S[a];
        g_S[a] = run;
        run += t;
    }
    if (blockIdx.x == 0 && threadIdx.x < DK) {
        float rz = 0.f;
        size_t zb = (size_t)bh * NCH * DK + threadIdx.x;
        for (int n = 0; n < NCH; n++) {
            size_t a = zb + (size_t)n * DK;
            float t = g_Z[a];
            g_Z[a] = rz;
            rz += t;
        }
    }
}

// ============================================================================
// Per-chunk output.
// ============================================================================
#define QS 132
#define AS 65

__global__ void __launch_bounds__(256) chunk_out_kernel(const float* __restrict__ g_w)
{
    extern __shared__ float sm[];
    float* q_s    = sm;
    float* k_s    = sm + 8448;
    float* v_s    = sm + 16896;
    float* S_s    = sm + 25344;
    float* attn_s = sm + 42240;
    float* Z_s    = sm + 46400;
    float* den_s  = sm + 46528;
    float* red_s  = sm + 46784;

    const int tid = threadIdx.x;
    const int n  = blockIdx.x;
    const int bh = blockIdx.y;
    const int b  = bh >> 3, h = bh & 7;
    const int row0 = b * TT + n * CH;
    const int col0 = h * DK;

    #pragma unroll
    for (int i = 0; i < 8; i++) {
        int lin = tid + i * 256;
        int r = lin >> 5;
        int c = (lin & 31) << 2;
        size_t src = (size_t)(row0 + r) * DD + col0 + c;
        *(float4*)&q_s[r * QS + c] = *(const float4*)&g_fq[src];
        *(float4*)&k_s[r * QS + c] = *(const float4*)&g_fk[src];
        *(float4*)&v_s[r * QS + c] = *(const float4*)&g_v[src];
    }
    size_t sbase = ((size_t)bh * NCH + n) * (DK * DV);
    #pragma unroll
    for (int i = 0; i < 16; i++) {
        int lin = tid + i * 256;
        int d = lin >> 5;
        int c = (lin & 31) << 2;
        *(float4*)&S_s[d * QS + c] = *(const float4*)&g_S[sbase + (size_t)d * DV + c];
    }
    if (tid < 32)
        *(float4*)&Z_s[tid * 4] = *(const float4*)&g_Z[((size_t)bh * NCH + n) * DK + tid * 4];
    __syncthreads();

    const int r  = tid >> 2;
    const int mq = tid & 3;
    {
        float denp = 0.f;
        for (int mm = 0; mm < 16; mm++) {
            int m = mq * 16 + mm;
            float a = 0.f;
            if (m <= r) {
                #pragma unroll 8
                for (int d4 = 0; d4 < 32; d4++) {
                    float4 qv = *(float4*)&q_s[r * QS + d4 * 4];
                    float4 kv = *(float4*)&k_s[m * QS + d4 * 4];
                    a += qv.x * kv.x + qv.y * kv.y + qv.z * kv.z + qv.w * kv.w;
                }
                denp += a;
            }
            attn_s[r * AS + m] = (m <= r) ? a : 0.f;
        }
        #pragma unroll 8
        for (int d = mq * 32; d < mq * 32 + 32; d++)
            denp += q_s[r * QS + d] * Z_s[d];
        den_s[tid] = denp;
    }
    __syncthreads();

    const int ty = tid >> 4;
    const int tx = tid & 15;
    const int e0 = tx * 8;
    float acc[4][8];
    #pragma unroll
    for (int i = 0; i < 4; i++)
        #pragma unroll
        for (int j = 0; j < 8; j++) acc[i][j] = 0.f;

    for (int m = 0; m < 64; m++) {
        float4 va = *(float4*)&v_s[m * QS + e0];
        float4 vb = *(float4*)&v_s[m * QS + e0 + 4];
        #pragma unroll
        for (int i = 0; i < 4; i++) {
            float a = attn_s[(ty * 4 + i) * AS + m];
            acc[i][0] = fmaf(a, va.x, acc[i][0]);
            acc[i][1] = fmaf(a, va.y, acc[i][1]);
            acc[i][2] = fmaf(a, va.z, acc[i][2]);
            acc[i][3] = fmaf(a, va.w, acc[i][3]);
            acc[i][4] = fmaf(a, vb.x, acc[i][4]);
            acc[i][5] = fmaf(a, vb.y, acc[i][5]);
            acc[i][6] = fmaf(a, vb.z, acc[i][6]);
            acc[i][7] = fmaf(a, vb.w, acc[i][7]);
        }
    }
    for (int d = 0; d < 128; d++) {
        float4 sa = *(float4*)&S_s[d * QS + e0];
        float4 sb2 = *(float4*)&S_s[d * QS + e0 + 4];
        #pragma unroll
        for (int i = 0; i < 4; i++) {
            float qv = q_s[(ty * 4 + i) * QS + d];
            acc[i][0] = fmaf(qv, sa.x, acc[i][0]);
            acc[i][1] = fmaf(qv, sa.y, acc[i][1]);
            acc[i][2] = fmaf(qv, sa.z, acc[i][2]);
            acc[i][3] = fmaf(qv, sa.w, acc[i][3]);
            acc[i][4] = fmaf(qv, sb2.x, acc[i][4]);
            acc[i][5] = fmaf(qv, sb2.y, acc[i][5]);
            acc[i][6] = fmaf(qv, sb2.z, acc[i][6]);
            acc[i][7] = fmaf(qv, sb2.w, acc[i][7]);
        }
    }
    float* o_s = k_s;
    #pragma unroll
    for (int i = 0; i < 4; i++) {
        *(float4*)&o_s[(ty * 4 + i) * QS + e0]     = make_float4(acc[i][0], acc[i][1], acc[i][2], acc[i][3]);
        *(float4*)&o_s[(ty * 4 + i) * QS + e0 + 4] = make_float4(acc[i][4], acc[i][5], acc[i][6], acc[i][7]);
    }
    __syncthreads();

    float den = den_s[r * 4 + 0] + den_s[r * 4 + 1] + den_s[r * 4 + 2] + den_s[r * 4 + 3];
    float dinv = 1.f / (den + 1e-6f);
    float pp = 0.f;
    #pragma unroll 8
    for (int e = mq * 32; e < mq * 32 + 32; e++) {
        float val = o_s[r * QS + e] * dinv;
        pp += val * val;
    }
    red_s[tid] = pp;
    __syncthreads();
    float ms  = (red_s[r * 4 + 0] + red_s[r * 4 + 1] + red_s[r * 4 + 2] + red_s[r * 4 + 3]) * (1.f / 128.f);
    float rms = rsqrtf(ms + 1e-5f);
    #pragma unroll 8
    for (int e = mq * 32; e < mq * 32 + 32; e++) {
        g_o[(size_t)(row0 + r) * DD + col0 + e] = o_s[r * QS + e] * dinv * rms * g_w[e];
    }
}

// ============================================================================
// launch
// ============================================================================
extern "C" void kernel_launch(void* const* d_in, const int* in_sizes, int n_in,
                              void* d_out, int out_size)
{
    const float* x    = (const float*)d_in[0];
    const float* Wq   = (const float*)d_in[1];
    const float* Wk   = (const float*)d_in[2];
    const float* Wv   = (const float*)d_in[3];
    const float* Wo   = (const float*)d_in[4];
    const float* fq1w = (const float*)d_in[5];
    const float* fq1b = (const float*)d_in[6];
    const float* fq2w = (const float*)d_in[7];
    const float* fq2b = (const float*)d_in[8];
    const float* fk1w = (const float*)d_in[9];
    const float* fk1b = (const float*)d_in[10];
    const float* fk2w = (const float*)d_in[11];
    const float* fk2b = (const float*)d_in[12];
    const float* gw   = (const float*)d_in[13];
    float* out = (float*)d_out;

    cudaFuncSetAttribute(chunk_kv_kernel,  cudaFuncAttributeMaxDynamicSharedMemorySize, 65536);
    cudaFuncSetAttribute(chunk_out_kernel, cudaFuncAttributeMaxDynamicSharedMemorySize, 188160);
    cudaFuncSetAttribute(mma_gemm_kernel,  cudaFuncAttributeMaxDynamicSharedMemorySize, MG_SMEM);
    cudaFuncSetAttribute(featmap_mma_kernel, cudaFuncAttributeMaxDynamicSharedMemorySize, FM_SMEM);

    float *q_p, *k_p, *v_p, *fq_p, *fk_p, *o_p;
    __nv_bfloat16 *ahi_p, *alo_p, *wthi_p, *wtlo_p, *fwhi_p, *fwlo_p;
    cudaGetSymbolAddress((void**)&q_p,  g_q);
    cudaGetSymbolAddress((void**)&k_p,  g_k);
    cudaGetSymbolAddress((void**)&v_p,  g_v);
    cudaGetSymbolAddress((void**)&fq_p, g_fq);
    cudaGetSymbolAddress((void**)&fk_p, g_fk);
    cudaGetSymbolAddress((void**)&o_p,  g_o);
    cudaGetSymbolAddress((void**)&ahi_p, g_ahi);
    cudaGetSymbolAddress((void**)&alo_p, g_alo);
    cudaGetSymbolAddress((void**)&wthi_p, g_wthi);
    cudaGetSymbolAddress((void**)&wtlo_p, g_wtlo);
    cudaGetSymbolAddress((void**)&fwhi_p, g_fwhi);
    cudaGetSymbolAddress((void**)&fwlo_p, g_fwlo);

    const size_t WSZ = (size_t)DD * DD;
    const int FWSZ = DK * DK;
    dim3 tblk(32, 8), tgrd(32, 32), tgrd128(4, 4);
    transpose_split_kernel<<<tgrd, tblk>>>(Wq, wthi_p + 0 * WSZ, wtlo_p + 0 * WSZ);
    transpose_split_kernel<<<tgrd, tblk>>>(Wk, wthi_p + 1 * WSZ, wtlo_p + 1 * WSZ);
    transpose_split_kernel<<<tgrd, tblk>>>(Wv, wthi_p + 2 * WSZ, wtlo_p + 2 * WSZ);
    transpose_split_kernel<<<tgrd, tblk>>>(Wo, wthi_p + 3 * WSZ, wtlo_p + 3 * WSZ);
    transpose_split128_kernel<<<tgrd128, tblk>>>(fq1w, fwhi_p + 0 * FWSZ, fwlo_p + 0 * FWSZ);
    transpose_split128_kernel<<<tgrd128, tblk>>>(fq2w, fwhi_p + 1 * FWSZ, fwlo_p + 1 * FWSZ);
    transpose_split128_kernel<<<tgrd128, tblk>>>(fk1w, fwhi_p + 2 * FWSZ, fwlo_p + 2 * FWSZ);
    transpose_split128_kernel<<<tgrd128, tblk>>>(fk2w, fwhi_p + 3 * FWSZ, fwlo_p + 3 * FWSZ);

    split_kernel<<<8192, 256>>>(x, ahi_p, alo_p);

    dim3 ggrid(DD / 128, TTOT / 128);  // (8, 128)
    mma_gemm_kernel<<<ggrid, 256, MG_SMEM>>>(ahi_p, alo_p, wthi_p + 0 * WSZ, wtlo_p + 0 * WSZ, q_p);
    mma_gemm_kernel<<<ggrid, 256, MG_SMEM>>>(ahi_p, alo_p, wthi_p + 1 * WSZ, wtlo_p + 1 * WSZ, k_p);
    mma_gemm_kernel<<<ggrid, 256, MG_SMEM>>>(ahi_p, alo_p, wthi_p + 2 * WSZ, wtlo_p + 2 * WSZ, v_p);

    dim3 fgrid(TTOT / 128, HH);        // (128, 8)
    featmap_mma_kernel<<<fgrid, 256, FM_SMEM>>>(
        q_p, fwhi_p + 0 * FWSZ, fwlo_p + 0 * FWSZ, fwhi_p + 1 * FWSZ, fwlo_p + 1 * FWSZ,
        fq1b, fq2b, fq_p, 0.08838834764831845f);
    featmap_mma_kernel<<<fgrid, 256, FM_SMEM>>>(
        k_p, fwhi_p + 2 * FWSZ, fwlo_p + 2 * FWSZ, fwhi_p + 3 * FWSZ, fwlo_p + 3 * FWSZ,
        fk1b, fk2b, fk_p, 1.0f);

    chunk_kv_kernel<<<dim3(NCH, BHN), 256, 65536>>>();
    scan_kernel<<<dim3(64, BHN), 256>>>();
    chunk_out_kernel<<<dim3(NCH, BHN), 256, 188160>>>(gw);

    split_kernel<<<8192, 256>>>(o_p, ahi_p, alo_p);
    mma_gemm_kernel<<<ggrid, 256, MG_SMEM>>>(ahi_p, alo_p, wthi_p + 3 * WSZ, wtlo_p + 3 * WSZ, out);
}

// round 7
// speedup vs baseline: 2.4674x; 1.1607x over previous
#include <cuda_runtime.h>
#include <cuda_bf16.h>
#include <cstdint>

// Problem constants
#define BB      2
#define TT      8192
#define DD      1024
#define HH      8
#define DK      128
#define DV      128
#define CH      64
#define NCH     128
#define BHN     16
#define TTOT    16384
#define NCHUNKS 2048

// -------- scratch (device globals; no allocation allowed) --------
__device__ float g_q [TTOT * DD];
__device__ float g_k [TTOT * DD];
__device__ float g_v [TTOT * DD];
__device__ float g_fq[TTOT * DD];
__device__ float g_fk[TTOT * DD];
__device__ float g_o [TTOT * DD];
__device__ float g_S [(size_t)NCHUNKS * DK * DV];   // holds S^T[e][d] per chunk
__device__ float g_Z [(size_t)NCHUNKS * DK];
__device__ __nv_bfloat16 g_ahi[(size_t)TTOT * DD];
__device__ __nv_bfloat16 g_alo[(size_t)TTOT * DD];
__device__ __nv_bfloat16 g_wthi[4ull * DD * DD];
__device__ __nv_bfloat16 g_wtlo[4ull * DD * DD];
__device__ __nv_bfloat16 g_fwhi[4 * DK * DK];
__device__ __nv_bfloat16 g_fwlo[4 * DK * DK];

// ============================================================================
// PTX helpers (sm_80+ only: cp.async, ldmatrix, mma.sync — assemble on sm_100)
// ============================================================================
__device__ __forceinline__ uint32_t smem_u32(const void* p) {
    uint32_t a;
    asm("{ .reg .u64 t; cvta.to.shared.u64 t, %1; cvt.u32.u64 %0, t; }" : "=r"(a) : "l"(p));
    return a;
}
#define CP_ASYNC16(dst_u32, src_ptr) \
    asm volatile("cp.async.cg.shared.global [%0], [%1], 16;" :: "r"(dst_u32), "l"(src_ptr) : "memory")
#define CP_COMMIT() asm volatile("cp.async.commit_group;" ::: "memory")
#define CP_WAIT(n)  asm volatile("cp.async.wait_group %0;" :: "n"(n) : "memory")

#define LDSM_X4(r0, r1, r2, r3, addr) \
    asm volatile("ldmatrix.sync.aligned.m8n8.x4.shared.b16 {%0,%1,%2,%3}, [%4];" \
        : "=r"(r0), "=r"(r1), "=r"(r2), "=r"(r3) : "r"(addr))

#define MMA16816(c, a, b) \
    asm volatile("mma.sync.aligned.m16n8k16.row.col.f32.bf16.bf16.f32 " \
        "{%0,%1,%2,%3}, {%4,%5,%6,%7}, {%8,%9}, {%0,%1,%2,%3};" \
        : "+f"((c)[0]), "+f"((c)[1]), "+f"((c)[2]), "+f"((c)[3]) \
        : "r"((a)[0]), "r"((a)[1]), "r"((a)[2]), "r"((a)[3]), "r"((b)[0]), "r"((b)[1]))

__device__ __forceinline__ void split2(float2 v, uint32_t& h, uint32_t& l) {
    __nv_bfloat16 h0 = __float2bfloat16(v.x), h1 = __float2bfloat16(v.y);
    __nv_bfloat16 l0 = __float2bfloat16(v.x - __bfloat162float(h0));
    __nv_bfloat16 l1 = __float2bfloat16(v.y - __bfloat162float(h1));
    __nv_bfloat162 hh = __halves2bfloat162(h0, h1);
    __nv_bfloat162 ll = __halves2bfloat162(l0, l1);
    h = *reinterpret_cast<uint32_t*>(&hh);
    l = *reinterpret_cast<uint32_t*>(&ll);
}
__device__ __forceinline__ void split4(float4 v, uint2& h, uint2& l) {
    uint32_t h0, l0, h1, l1;
    split2(make_float2(v.x, v.y), h0, l0);
    split2(make_float2(v.z, v.w), h1, l1);
    h = make_uint2(h0, h1); l = make_uint2(l0, l1);
}

// ============================================================================
// split kernels
// ============================================================================
__global__ void __launch_bounds__(256) split_kernel(
    const float* __restrict__ in, __nv_bfloat16* __restrict__ hi, __nv_bfloat16* __restrict__ lo)
{
    size_t idx = ((size_t)blockIdx.x * 256 + threadIdx.x) * 8;
    float4 a = *(const float4*)&in[idx];
    float4 b = *(const float4*)&in[idx + 4];
    float v[8] = {a.x, a.y, a.z, a.w, b.x, b.y, b.z, b.w};
    __nv_bfloat16 h[8], l[8];
    #pragma unroll
    for (int t = 0; t < 8; t++) {
        h[t] = __float2bfloat16(v[t]);
        l[t] = __float2bfloat16(v[t] - __bfloat162float(h[t]));
    }
    *(uint4*)&hi[idx] = *(uint4*)h;
    *(uint4*)&lo[idx] = *(uint4*)l;
}

__global__ void transpose_split_kernel(
    const float* __restrict__ W, __nv_bfloat16* __restrict__ hi, __nv_bfloat16* __restrict__ lo)
{
    __shared__ float ts[32][33];
    int tx = threadIdx.x, ty = threadIdx.y;
    int n0 = blockIdx.x * 32, k0 = blockIdx.y * 32;
    for (int i = ty; i < 32; i += 8) ts[i][tx] = W[(size_t)(k0 + i) * DD + n0 + tx];
    __syncthreads();
    for (int i = ty; i < 32; i += 8) {
        float v = ts[tx][i];
        __nv_bfloat16 h = __float2bfloat16(v);
        __nv_bfloat16 l = __float2bfloat16(v - __bfloat162float(h));
        size_t o = (size_t)(n0 + i) * DD + k0 + tx;
        hi[o] = h; lo[o] = l;
    }
}

__global__ void transpose_split128_kernel(
    const float* __restrict__ W, __nv_bfloat16* __restrict__ hi, __nv_bfloat16* __restrict__ lo)
{
    __shared__ float ts[32][33];
    int tx = threadIdx.x, ty = threadIdx.y;
    int n0 = blockIdx.x * 32, k0 = blockIdx.y * 32;
    for (int i = ty; i < 32; i += 8) ts[i][tx] = W[(k0 + i) * DK + n0 + tx];
    __syncthreads();
    for (int i = ty; i < 32; i += 8) {
        float v = ts[tx][i];
        __nv_bfloat16 h = __float2bfloat16(v);
        __nv_bfloat16 l = __float2bfloat16(v - __bfloat162float(h));
        int o = (n0 + i) * DK + k0 + tx;
        hi[o] = h; lo[o] = l;
    }
}

// ============================================================================
// mma.sync bf16 GEMM body (128x128 tile, BK=32, 3-stage cp.async) — validated
// ============================================================================
#define MG_STAGE 32768
#define MG_B_OFF 16384
#define MG_SMEM  (3 * MG_STAGE)

__device__ __forceinline__ void mg_load_stage(
    uint32_t stb, int tid, int kt, int rowBase, int colBase,
    const __nv_bfloat16* __restrict__ Ahi, const __nv_bfloat16* __restrict__ Alo,
    const __nv_bfloat16* __restrict__ Bhi, const __nv_bfloat16* __restrict__ Blo)
{
    #pragma unroll
    for (int j = 0; j < 8; j++) {
        int l = tid + j * 256;
        int isB = l >> 10;
        int ll = l & 1023;
        int r = ll >> 3, c = ll & 7;
        const __nv_bfloat16* g;
        int gr;
        if (!isB) { g = (c < 4) ? Ahi : Alo; gr = rowBase + r; }
        else      { g = (c < 4) ? Bhi : Blo; gr = colBase + r; }
        const void* src = g + (size_t)gr * DD + kt + (c & 3) * 8;
        uint32_t off = (uint32_t)(r * 128) + (((uint32_t)c * 16) ^ (((uint32_t)(r & 7)) << 4));
        CP_ASYNC16(stb + isB * MG_B_OFF + off, src);
    }
}

__device__ __forceinline__ void mg_body(
    uint32_t sb, int tid,
    const __nv_bfloat16* __restrict__ Ahi, const __nv_bfloat16* __restrict__ Alo,
    const __nv_bfloat16* __restrict__ Bhi, const __nv_bfloat16* __restrict__ Blo,
    float* __restrict__ C, int rowBase, int colBase)
{
    const int wid  = tid >> 5;
    const int lane = tid & 31;
    const int warp_m = wid >> 2;
    const int warp_n = wid & 3;

    mg_load_stage(sb + 0 * MG_STAGE, tid, 0,  rowBase, colBase, Ahi, Alo, Bhi, Blo);
    CP_COMMIT();
    mg_load_stage(sb + 1 * MG_STAGE, tid, 32, rowBase, colBase, Ahi, Alo, Bhi, Blo);
    CP_COMMIT();

    float acc[4][4][4];
    #pragma unroll
    for (int mi = 0; mi < 4; mi++)
        #pragma unroll
        for (int ni = 0; ni < 4; ni++)
            #pragma unroll
            for (int t = 0; t < 4; t++) acc[mi][ni][t] = 0.f;

    const int aRow  = warp_m * 64 + (lane & 7) + ((lane >> 3) & 1) * 8;
    const uint32_t aKB = ((lane >> 4) & 1) * 16;
    const int bRow  = warp_n * 32 + (lane & 7) + ((lane >> 4) & 1) * 8;
    const uint32_t bKB = ((lane >> 3) & 1) * 16;

    for (int ci = 0; ci < 32; ci++) {
        CP_WAIT(1);
        __syncthreads();
        if (ci + 2 < 32)
            mg_load_stage(sb + ((ci + 2) % 3) * MG_STAGE, tid, (ci + 2) * 32,
                          rowBase, colBase, Ahi, Alo, Bhi, Blo);
        CP_COMMIT();

        uint32_t stb = sb + (ci % 3) * MG_STAGE;
        #pragma unroll
        for (int j = 0; j < 2; j++) {
            uint32_t bh[4][2], bl[4][2];
            #pragma unroll
            for (int ni2 = 0; ni2 < 2; ni2++) {
                int nr = bRow + ni2 * 16;
                uint32_t rbase = stb + MG_B_OFF + nr * 128;
                uint32_t swz = ((uint32_t)(nr & 7)) << 4;
                uint32_t koff = j * 32 + bKB;
                LDSM_X4(bh[ni2 * 2][0], bh[ni2 * 2][1], bh[ni2 * 2 + 1][0], bh[ni2 * 2 + 1][1],
                        rbase + (koff ^ swz));
                LDSM_X4(bl[ni2 * 2][0], bl[ni2 * 2][1], bl[ni2 * 2 + 1][0], bl[ni2 * 2 + 1][1],
                        rbase + ((koff + 64) ^ swz));
            }
            #pragma unroll
            for (int mi = 0; mi < 4; mi++) {
                int ar = aRow + mi * 16;
                uint32_t rbase = stb + ar * 128;
                uint32_t swz = ((uint32_t)(ar & 7)) << 4;
                uint32_t koff = j * 32 + aKB;
                uint32_t ah[4], al[4];
                LDSM_X4(ah[0], ah[1], ah[2], ah[3], rbase + (koff ^ swz));
                LDSM_X4(al[0], al[1], al[2], al[3], rbase + ((koff + 64) ^ swz));
                #pragma unroll
                for (int ni = 0; ni < 4; ni++) {
                    MMA16816(acc[mi][ni], ah, bh[ni]);
                    MMA16816(acc[mi][ni], ah, bl[ni]);
                    MMA16816(acc[mi][ni], al, bh[ni]);
                }
            }
        }
    }

    #pragma unroll
    for (int mi = 0; mi < 4; mi++) {
        int r0 = rowBase + warp_m * 64 + mi * 16 + (lane >> 2);
        #pragma unroll
        for (int ni = 0; ni < 4; ni++) {
            int c0 = colBase + warp_n * 32 + ni * 8 + (lane & 3) * 2;
            *(float2*)&C[(size_t)r0 * DD + c0]       = make_float2(acc[mi][ni][0], acc[mi][ni][1]);
            *(float2*)&C[(size_t)(r0 + 8) * DD + c0] = make_float2(acc[mi][ni][2], acc[mi][ni][3]);
        }
    }
}

// merged q/k/v GEMM: blockIdx.x in [0,24): sel = x>>3 picks {Wq,Wk,Wv}
__global__ void __launch_bounds__(256, 2) qkv_gemm_kernel(
    const __nv_bfloat16* __restrict__ Ahi, const __nv_bfloat16* __restrict__ Alo,
    const __nv_bfloat16* __restrict__ Bhi0, const __nv_bfloat16* __restrict__ Blo0,
    float* __restrict__ C0, float* __restrict__ C1, float* __restrict__ C2)
{
    extern __shared__ __align__(1024) char smem[];
    uint32_t sb = smem_u32(smem);
    int sel = blockIdx.x >> 3;
    int colBase = (blockIdx.x & 7) * 128;
    const size_t WSZ = (size_t)DD * DD;
    const __nv_bfloat16* Bhi = Bhi0 + (size_t)sel * WSZ;
    const __nv_bfloat16* Blo = Blo0 + (size_t)sel * WSZ;
    float* C = (sel == 0) ? C0 : (sel == 1) ? C1 : C2;
    mg_body(sb, threadIdx.x, Ahi, Alo, Bhi, Blo, C, blockIdx.y * 128, colBase);
}

__global__ void __launch_bounds__(256, 2) mma_gemm_kernel(
    const __nv_bfloat16* __restrict__ Ahi, const __nv_bfloat16* __restrict__ Alo,
    const __nv_bfloat16* __restrict__ Bhi, const __nv_bfloat16* __restrict__ Blo,
    float* __restrict__ C)
{
    extern __shared__ __align__(1024) char smem[];
    uint32_t sb = smem_u32(smem);
    mg_body(sb, threadIdx.x, Ahi, Alo, Bhi, Blo, C, blockIdx.y * 128, blockIdx.x * 128);
}

// ============================================================================
// featmap via mma.sync (validated in Round 6)
// ============================================================================
#define FM_AS   132
#define FM_WSB  272
#define FM_W1H  67584
#define FM_W1L  (FM_W1H + 34816)
#define FM_W2H  (FM_W1L + 34816)
#define FM_W2L  (FM_W2H + 34816)
#define FM_SMEM (FM_W2L + 34816)

__global__ void __launch_bounds__(256) featmap_mma_kernel(
    const float* __restrict__ in,
    const __nv_bfloat16* __restrict__ w1hi, const __nv_bfloat16* __restrict__ w1lo,
    const __nv_bfloat16* __restrict__ w2hi, const __nv_bfloat16* __restrict__ w2lo,
    const float* __restrict__ b1, const float* __restrict__ b2,
    float* __restrict__ out, float scale)
{
    extern __shared__ __align__(16) char smem[];
    float* A_s = (float*)smem;
    const int tid = threadIdx.x, wid = tid >> 5, lane = tid & 31;
    const int row0 = blockIdx.x * 128;
    const int h = blockIdx.y;
    const size_t base = (size_t)row0 * DD + h * DK;

    #pragma unroll
    for (int i = 0; i < 16; i++) {
        int lin = tid + i * 256;
        int r = lin >> 5, c = (lin & 31) * 4;
        *(float4*)&A_s[r * FM_AS + c] = *(const float4*)&in[base + (size_t)r * DD + c];
    }
    #pragma unroll
    for (int i = 0; i < 8; i++) {
        int lin = tid + i * 256;
        int r = lin >> 4, c8 = lin & 15;
        int gsrc = r * DK + c8 * 8;
        uint32_t doff = (uint32_t)r * FM_WSB + c8 * 16;
        *(uint4*)(smem + FM_W1H + doff) = *(const uint4*)&w1hi[gsrc];
        *(uint4*)(smem + FM_W1L + doff) = *(const uint4*)&w1lo[gsrc];
        *(uint4*)(smem + FM_W2H + doff) = *(const uint4*)&w2hi[gsrc];
        *(uint4*)(smem + FM_W2L + doff) = *(const uint4*)&w2lo[gsrc];
    }
    __syncthreads();

    const int m0 = wid * 16;
    float acc1[16][4], acc2[16][4];
    #pragma unroll
    for (int ni = 0; ni < 16; ni++)
        #pragma unroll
        for (int t = 0; t < 4; t++) { acc1[ni][t] = 0.f; acc2[ni][t] = 0.f; }

    const int ar  = m0 + (lane >> 2);
    const int akc = (lane & 3) * 2;
    const int bn  = lane >> 2;

    for (int kk = 0; kk < 8; kk++) {
        int k0 = kk * 16;
        uint32_t ah[4], al[4];
        split2(*(float2*)&A_s[ar * FM_AS + k0 + akc],           ah[0], al[0]);
        split2(*(float2*)&A_s[(ar + 8) * FM_AS + k0 + akc],     ah[1], al[1]);
        split2(*(float2*)&A_s[ar * FM_AS + k0 + 8 + akc],       ah[2], al[2]);
        split2(*(float2*)&A_s[(ar + 8) * FM_AS + k0 + 8 + akc], ah[3], al[3]);

        uint32_t kb = (uint32_t)(k0 + akc) * 2;
        #pragma unroll
        for (int ni = 0; ni < 16; ni++) {
            uint32_t roff = (uint32_t)(ni * 8 + bn) * FM_WSB + kb;
            uint32_t w1h[2], w1l[2], w2h[2], w2l[2];
            w1h[0] = *(uint32_t*)(smem + FM_W1H + roff);
            w1h[1] = *(uint32_t*)(smem + FM_W1H + roff + 16);
            w1l[0] = *(uint32_t*)(smem + FM_W1L + roff);
            w1l[1] = *(uint32_t*)(smem + FM_W1L + roff + 16);
            w2h[0] = *(uint32_t*)(smem + FM_W2H + roff);
            w2h[1] = *(uint32_t*)(smem + FM_W2H + roff + 16);
            w2l[0] = *(uint32_t*)(smem + FM_W2L + roff);
            w2l[1] = *(uint32_t*)(smem + FM_W2L + roff + 16);
            MMA16816(acc1[ni], ah, w1h);
            MMA16816(acc1[ni], ah, w1l);
            MMA16816(acc1[ni], al, w1h);
            MMA16816(acc2[ni], ah, w2h);
            MMA16816(acc2[ni], ah, w2l);
            MMA16816(acc2[ni], al, w2h);
        }
    }

    const int orow = row0 + m0 + (lane >> 2);
    #pragma unroll
    for (int ni = 0; ni < 16; ni++) {
        int col = ni * 8 + (lane & 3) * 2;
        float2 bb1 = *(const float2*)&b1[col];
        float2 bb2 = *(const float2*)&b2[col];
        float o0 = (acc1[ni][0] + bb1.x) * (acc2[ni][0] + bb2.x) * scale;
        float o1 = (acc1[ni][1] + bb1.y) * (acc2[ni][1] + bb2.y) * scale;
        float o2 = (acc1[ni][2] + bb1.x) * (acc2[ni][2] + bb2.x) * scale;
        float o3 = (acc1[ni][3] + bb1.y) * (acc2[ni][3] + bb2.y) * scale;
        *(float2*)&out[(size_t)orow * DD + h * DK + col]       = make_float2(o0, o1);
        *(float2*)&out[(size_t)(orow + 8) * DD + h * DK + col] = make_float2(o2, o3);
    }
}

// ============================================================================
// chunk_kv via MMA: S_T[e][d] = sum_t v[t][e]*fk[t][d]  (+ Z[d] = sum_t fk[t][d])
// Stage fkT[d][t], vT[e][t] bf16 hi/lo (stride 72). M=128(e), N=128(d), K=64(t).
// ============================================================================
#define KV_FKT_HI 0
#define KV_FKT_LO 18432
#define KV_VT_HI  36864
#define KV_VT_LO  55296
#define KV_SMEM   73728
#define KV_WS     72    // bf16 stride

__global__ void __launch_bounds__(256) chunk_kv_mma_kernel()
{
    extern __shared__ __align__(16) char smem[];
    const int tid = threadIdx.x, wid = tid >> 5, lane = tid & 31;
    const int n  = blockIdx.x;
    const int bh = blockIdx.y;
    const int b  = bh >> 3, h = bh & 7;
    const int row0 = b * TT + n * CH;
    const int col0 = h * DK;

    // transposed split staging
    #pragma unroll
    for (int i = 0; i < 8; i++) {
        int lin = tid + i * 256;                 // 0..2047
        int t = lin >> 5, c4 = (lin & 31) * 4;
        size_t src = (size_t)(row0 + t) * DD + col0 + c4;
        float4 kv = *(const float4*)&g_fk[src];
        float4 vv = *(const float4*)&g_v[src];
        float kk[4] = {kv.x, kv.y, kv.z, kv.w};
        float vw[4] = {vv.x, vv.y, vv.z, vv.w};
        #pragma unroll
        for (int j = 0; j < 4; j++) {
            __nv_bfloat16 kh = __float2bfloat16(kk[j]);
            __nv_bfloat16 kl = __float2bfloat16(kk[j] - __bfloat162float(kh));
            __nv_bfloat16 vh = __float2bfloat16(vw[j]);
            __nv_bfloat16 vl = __float2bfloat16(vw[j] - __bfloat162float(vh));
            int off = (c4 + j) * KV_WS + t;
            *(__nv_bfloat16*)(smem + KV_FKT_HI + off * 2) = kh;
            *(__nv_bfloat16*)(smem + KV_FKT_LO + off * 2) = kl;
            *(__nv_bfloat16*)(smem + KV_VT_HI  + off * 2) = vh;
            *(__nv_bfloat16*)(smem + KV_VT_LO  + off * 2) = vl;
        }
    }
    __syncthreads();

    const int m0 = (wid & 3) * 32;   // e
    const int n0 = (wid >> 2) * 64;  // d
    const int lr = lane >> 2, lk = (lane & 3) * 2;

    float acc[2][8][4];
    #pragma unroll
    for (int mi = 0; mi < 2; mi++)
        #pragma unroll
        for (int ni = 0; ni < 8; ni++)
            #pragma unroll
            for (int t = 0; t < 4; t++) acc[mi][ni][t] = 0.f;

    #pragma unroll
    for (int kk = 0; kk < 4; kk++) {
        int k0 = kk * 16;
        #pragma unroll
        for (int mi = 0; mi < 2; mi++) {
            int mr = m0 + mi * 16 + lr;
            uint32_t ah[4], al[4];
            ah[0] = *(uint32_t*)(smem + KV_VT_HI + (mr * KV_WS + k0 + lk) * 2);
            ah[1] = *(uint32_t*)(smem + KV_VT_HI + ((mr + 8) * KV_WS + k0 + lk) * 2);
            ah[2] = *(uint32_t*)(smem + KV_VT_HI + (mr * KV_WS + k0 + 8 + lk) * 2);
            ah[3] = *(uint32_t*)(smem + KV_VT_HI + ((mr + 8) * KV_WS + k0 + 8 + lk) * 2);
            al[0] = *(uint32_t*)(smem + KV_VT_LO + (mr * KV_WS + k0 + lk) * 2);
            al[1] = *(uint32_t*)(smem + KV_VT_LO + ((mr + 8) * KV_WS + k0 + lk) * 2);
            al[2] = *(uint32_t*)(smem + KV_VT_LO + (mr * KV_WS + k0 + 8 + lk) * 2);
            al[3] = *(uint32_t*)(smem + KV_VT_LO + ((mr + 8) * KV_WS + k0 + 8 + lk) * 2);
            #pragma unroll
            for (int ni = 0; ni < 8; ni++) {
                int nr = n0 + ni * 8 + lr;
                uint32_t bh[2], bl[2];
                bh[0] = *(uint32_t*)(smem + KV_FKT_HI + (nr * KV_WS + k0 + lk) * 2);
                bh[1] = *(uint32_t*)(smem + KV_FKT_HI + (nr * KV_WS + k0 + 8 + lk) * 2);
                bl[0] = *(uint32_t*)(smem + KV_FKT_LO + (nr * KV_WS + k0 + lk) * 2);
                bl[1] = *(uint32_t*)(smem + KV_FKT_LO + (nr * KV_WS + k0 + 8 + lk) * 2);
                MMA16816(acc[mi][ni], ah, bh);
                MMA16816(acc[mi][ni], ah, bl);
                MMA16816(acc[mi][ni], al, bh);
            }
        }
    }

    size_t sb = ((size_t)bh * NCH + n) * (DK * DV);
    #pragma unroll
    for (int mi = 0; mi < 2; mi++) {
        int e0 = m0 + mi * 16 + lr;
        #pragma unroll
        for (int ni = 0; ni < 8; ni++) {
            int d = n0 + ni * 8 + lk;
            *(float2*)&g_S[sb + (size_t)e0 * DV + d]       = make_float2(acc[mi][ni][0], acc[mi][ni][1]);
            *(float2*)&g_S[sb + (size_t)(e0 + 8) * DV + d] = make_float2(acc[mi][ni][2], acc[mi][ni][3]);
        }
    }

    if (tid < 128) {
        float s = 0.f;
        #pragma unroll 8
        for (int t = 0; t < 64; t++) {
            s += __bfloat162float(*(__nv_bfloat16*)(smem + KV_FKT_HI + (tid * KV_WS + t) * 2))
               + __bfloat162float(*(__nv_bfloat16*)(smem + KV_FKT_LO + (tid * KV_WS + t) * 2));
        }
        g_Z[((size_t)bh * NCH + n) * DK + tid] = s;
    }
}

// ============================================================================
// Exclusive prefix scan over chunks (elementwise — layout-agnostic).
// ============================================================================
__global__ void __launch_bounds__(256) scan_kernel()
{
    const int bh  = blockIdx.y;
    const int idx = blockIdx.x * 256 + threadIdx.x;

    float run = 0.f;
    size_t base = (size_t)bh * NCH * (DK * DV) + idx;
    for (int n = 0; n < NCH; n++) {
        size_t a = base + (size_t)n * (DK * DV);
        float t = g_S[a];
        g_S[a] = run;
        run += t;
    }
    if (blockIdx.x == 0 && threadIdx.x < DK) {
        float rz = 0.f;
        size_t zb = (size_t)bh * NCH * DK + threadIdx.x;
        for (int n = 0; n < NCH; n++) {
            size_t a = zb + (size_t)n * DK;
            float t = g_Z[a];
            g_Z[a] = rz;
            rz += t;
        }
    }
}

// ============================================================================
// chunk_out via MMA:
//   attn = tril(fq@fk^T)   [MMA, phase A]
//   o    = attn@v + fq@S   [fq@S via MMA phase B (S stored transposed), attn@v FFMA]
//   den  = rowsum(attn) + fq.Z ; normalize + RMSNorm
// ============================================================================
#define CO_FQ_HI 0
#define CO_FQ_LO 17408
#define CO_FK_HI 34816              // overlaid by o_s (fp32 64x132 = 33792 B) after phase A
#define CO_FK_LO 52224
#define CO_V     69632              // fp32 64x132
#define CO_S_HI  103424             // bf16 128x136
#define CO_S_LO  138240
#define CO_ATTN  173056             // fp32 64x68
#define CO_Z     190464             // fp32 128
#define CO_DEN   190976             // fp32 256
#define CO_RED   192000             // fp32 256
#define CO_SMEM  193024
#define CO_WS    136                // bf16 stride
#define CO_VS    132                // fp32 stride
#define CO_AS2   68                 // attn fp32 stride

__global__ void __launch_bounds__(256) chunk_out_mma_kernel(const float* __restrict__ g_w)
{
    extern __shared__ __align__(16) char smem[];
    const int tid = threadIdx.x, wid = tid >> 5, lane = tid & 31;
    const int n  = blockIdx.x;
    const int bh = blockIdx.y;
    const int b  = bh >> 3, h = bh & 7;
    const int row0 = b * TT + n * CH;
    const int col0 = h * DK;

    float* v_s    = (float*)(smem + CO_V);
    float* attn_s = (float*)(smem + CO_ATTN);
    float* Z_s    = (float*)(smem + CO_Z);
    float* den_s  = (float*)(smem + CO_DEN);
    float* red_s  = (float*)(smem + CO_RED);

    // ---- staging ----
    #pragma unroll
    for (int i = 0; i < 8; i++) {
        int lin = tid + i * 256;
        int r = lin >> 5, c4 = (lin & 31) * 4;
        size_t src = (size_t)(row0 + r) * DD + col0 + c4;
        uint2 hh, ll;
        split4(*(const float4*)&g_fq[src], hh, ll);
        *(uint2*)(smem + CO_FQ_HI + (r * CO_WS + c4) * 2) = hh;
        *(uint2*)(smem + CO_FQ_LO + (r * CO_WS + c4) * 2) = ll;
        split4(*(const float4*)&g_fk[src], hh, ll);
        *(uint2*)(smem + CO_FK_HI + (r * CO_WS + c4) * 2) = hh;
        *(uint2*)(smem + CO_FK_LO + (r * CO_WS + c4) * 2) = ll;
        *(float4*)&v_s[r * CO_VS + c4] = *(const float4*)&g_v[src];
    }
    size_t sbase = ((size_t)bh * NCH + n) * (DK * DV);
    #pragma unroll
    for (int i = 0; i < 16; i++) {
        int lin = tid + i * 256;
        int r = lin >> 5, c4 = (lin & 31) * 4;   // r = e (0..127), c4 = d
        uint2 hh, ll;
        split4(*(const float4*)&g_S[sbase + (size_t)r * DV + c4], hh, ll);
        *(uint2*)(smem + CO_S_HI + (r * CO_WS + c4) * 2) = hh;
        *(uint2*)(smem + CO_S_LO + (r * CO_WS + c4) * 2) = ll;
    }
    if (tid < 32)
        *(float4*)&Z_s[tid * 4] = *(const float4*)&g_Z[((size_t)bh * NCH + n) * DK + tid * 4];
    __syncthreads();

    const int lr = lane >> 2, lk = (lane & 3) * 2;

    // ---- phase A: attn = fq @ fk^T  (M=64, N=64, K=128) ----
    {
        const int m0 = (wid & 3) * 16;
        const int n0 = (wid >> 2) * 32;
        float acc[4][4];
        #pragma unroll
        for (int ni = 0; ni < 4; ni++)
            #pragma unroll
            for (int t = 0; t < 4; t++) acc[ni][t] = 0.f;

        #pragma unroll
        for (int kk = 0; kk < 8; kk++) {
            int k0 = kk * 16;
            int mr = m0 + lr;
            uint32_t ah[4], al[4];
            ah[0] = *(uint32_t*)(smem + CO_FQ_HI + (mr * CO_WS + k0 + lk) * 2);
            ah[1] = *(uint32_t*)(smem + CO_FQ_HI + ((mr + 8) * CO_WS + k0 + lk) * 2);
            ah[2] = *(uint32_t*)(smem + CO_FQ_HI + (mr * CO_WS + k0 + 8 + lk) * 2);
            ah[3] = *(uint32_t*)(smem + CO_FQ_HI + ((mr + 8) * CO_WS + k0 + 8 + lk) * 2);
            al[0] = *(uint32_t*)(smem + CO_FQ_LO + (mr * CO_WS + k0 + lk) * 2);
            al[1] = *(uint32_t*)(smem + CO_FQ_LO + ((mr + 8) * CO_WS + k0 + lk) * 2);
            al[2] = *(uint32_t*)(smem + CO_FQ_LO + (mr * CO_WS + k0 + 8 + lk) * 2);
            al[3] = *(uint32_t*)(smem + CO_FQ_LO + ((mr + 8) * CO_WS + k0 + 8 + lk) * 2);
            #pragma unroll
            for (int ni = 0; ni < 4; ni++) {
                int nr = n0 + ni * 8 + lr;
                uint32_t bh[2], bl[2];
                bh[0] = *(uint32_t*)(smem + CO_FK_HI + (nr * CO_WS + k0 + lk) * 2);
                bh[1] = *(uint32_t*)(smem + CO_FK_HI + (nr * CO_WS + k0 + 8 + lk) * 2);
                bl[0] = *(uint32_t*)(smem + CO_FK_LO + (nr * CO_WS + k0 + lk) * 2);
                bl[1] = *(uint32_t*)(smem + CO_FK_LO + (nr * CO_WS + k0 + 8 + lk) * 2);
                MMA16816(acc[ni], ah, bh);
                MMA16816(acc[ni], ah, bl);
                MMA16816(acc[ni], al, bh);
            }
        }
        // write attn with causal mask
        int r0 = m0 + lr, r1 = r0 + 8;
        #pragma unroll
        for (int ni = 0; ni < 4; ni++) {
            int c = n0 + ni * 8 + lk;
            attn_s[r0 * CO_AS2 + c]     = (c     <= r0) ? acc[ni][0] : 0.f;
            attn_s[r0 * CO_AS2 + c + 1] = (c + 1 <= r0) ? acc[ni][1] : 0.f;
            attn_s[r1 * CO_AS2 + c]     = (c     <= r1) ? acc[ni][2] : 0.f;
            attn_s[r1 * CO_AS2 + c + 1] = (c + 1 <= r1) ? acc[ni][3] : 0.f;
        }
    }
    __syncthreads();   // fk reads done; attn published

    // ---- phase B: o_inter = fq @ S  (B = S_T[e][d] row-major; M=64, N=128, K=128) ----
    float* o_s = (float*)(smem + CO_FK_HI);   // overlays fk (dead)
    {
        const int m0 = (wid & 3) * 16;
        const int n0 = (wid >> 2) * 64;
        float acc[8][4];
        #pragma unroll
        for (int ni = 0; ni < 8; ni++)
            #pragma unroll
            for (int t = 0; t < 4; t++) acc[ni][t] = 0.f;

        #pragma unroll
        for (int kk = 0; kk < 8; kk++) {
            int k0 = kk * 16;
            int mr = m0 + lr;
            uint32_t ah[4], al[4];
            ah[0] = *(uint32_t*)(smem + CO_FQ_HI + (mr * CO_WS + k0 + lk) * 2);
            ah[1] = *(uint32_t*)(smem + CO_FQ_HI + ((mr + 8) * CO_WS + k0 + lk) * 2);
            ah[2] = *(uint32_t*)(smem + CO_FQ_HI + (mr * CO_WS + k0 + 8 + lk) * 2);
            ah[3] = *(uint32_t*)(smem + CO_FQ_HI + ((mr + 8) * CO_WS + k0 + 8 + lk) * 2);
            al[0] = *(uint32_t*)(smem + CO_FQ_LO + (mr * CO_WS + k0 + lk) * 2);
            al[1] = *(uint32_t*)(smem + CO_FQ_LO + ((mr + 8) * CO_WS + k0 + lk) * 2);
            al[2] = *(uint32_t*)(smem + CO_FQ_LO + (mr * CO_WS + k0 + 8 + lk) * 2);
            al[3] = *(uint32_t*)(smem + CO_FQ_LO + ((mr + 8) * CO_WS + k0 + 8 + lk) * 2);
            #pragma unroll
            for (int ni = 0; ni < 8; ni++) {
                int nr = n0 + ni * 8 + lr;
                uint32_t bh[2], bl[2];
                bh[0] = *(uint32_t*)(smem + CO_S_HI + (nr * CO_WS + k0 + lk) * 2);
                bh[1] = *(uint32_t*)(smem + CO_S_HI + (nr * CO_WS + k0 + 8 + lk) * 2);
                bl[0] = *(uint32_t*)(smem + CO_S_LO + (nr * CO_WS + k0 + lk) * 2);
                bl[1] = *(uint32_t*)(smem + CO_S_LO + (nr * CO_WS + k0 + 8 + lk) * 2);
                MMA16816(acc[ni], ah, bh);
                MMA16816(acc[ni], ah, bl);
                MMA16816(acc[ni], al, bh);
            }
        }
        int r0 = m0 + lr;
        #pragma unroll
        for (int ni = 0; ni < 8; ni++) {
            int c = n0 + ni * 8 + lk;
            *(float2*)&o_s[r0 * CO_VS + c]       = make_float2(acc[ni][0], acc[ni][1]);
            *(float2*)&o_s[(r0 + 8) * CO_VS + c] = make_float2(acc[ni][2], acc[ni][3]);
        }
    }
    __syncthreads();

    // ---- phase C1: o += attn @ v  (4 rows x 8 cols per thread) ----
    {
        const int ty = tid >> 4;
        const int tx = tid & 15;
        const int e0 = tx * 8;
        float acc[4][8];
        #pragma unroll
        for (int i = 0; i < 4; i++) {
            float4 a0 = *(float4*)&o_s[(ty * 4 + i) * CO_VS + e0];
            float4 a1 = *(float4*)&o_s[(ty * 4 + i) * CO_VS + e0 + 4];
            acc[i][0] = a0.x; acc[i][1] = a0.y; acc[i][2] = a0.z; acc[i][3] = a0.w;
            acc[i][4] = a1.x; acc[i][5] = a1.y; acc[i][6] = a1.z; acc[i][7] = a1.w;
        }
        for (int m = 0; m < 64; m++) {
            float4 va = *(float4*)&v_s[m * CO_VS + e0];
            float4 vb = *(float4*)&v_s[m * CO_VS + e0 + 4];
            #pragma unroll
            for (int i = 0; i < 4; i++) {
                float a = attn_s[(ty * 4 + i) * CO_AS2 + m];
                acc[i][0] = fmaf(a, va.x, acc[i][0]);
                acc[i][1] = fmaf(a, va.y, acc[i][1]);
                acc[i][2] = fmaf(a, va.z, acc[i][2]);
                acc[i][3] = fmaf(a, va.w, acc[i][3]);
                acc[i][4] = fmaf(a, vb.x, acc[i][4]);
                acc[i][5] = fmaf(a, vb.y, acc[i][5]);
                acc[i][6] = fmaf(a, vb.z, acc[i][6]);
                acc[i][7] = fmaf(a, vb.w, acc[i][7]);
            }
        }
        #pragma unroll
        for (int i = 0; i < 4; i++) {
            *(float4*)&o_s[(ty * 4 + i) * CO_VS + e0]     = make_float4(acc[i][0], acc[i][1], acc[i][2], acc[i][3]);
            *(float4*)&o_s[(ty * 4 + i) * CO_VS + e0 + 4] = make_float4(acc[i][4], acc[i][5], acc[i][6], acc[i][7]);
        }
    }
    __syncthreads();

    // ---- phase C2: den + normalize + RMSNorm + writeout ----
    {
        const int r  = tid >> 2;
        const int mq = tid & 3;
        float denp = 0.f;
        #pragma unroll 8
        for (int m = mq * 16; m < mq * 16 + 16; m++)
            denp += attn_s[r * CO_AS2 + m];
        #pragma unroll 8
        for (int d = mq * 32; d < mq * 32 + 32; d++) {
            float qv = __bfloat162float(*(__nv_bfloat16*)(smem + CO_FQ_HI + (r * CO_WS + d) * 2))
                     + __bfloat162float(*(__nv_bfloat16*)(smem + CO_FQ_LO + (r * CO_WS + d) * 2));
            denp += qv * Z_s[d];
        }
        den_s[tid] = denp;
        __syncthreads();
        float den = den_s[r * 4 + 0] + den_s[r * 4 + 1] + den_s[r * 4 + 2] + den_s[r * 4 + 3];
        float dinv = 1.f / (den + 1e-6f);
        float pp = 0.f;
        #pragma unroll 8
        for (int e = mq * 32; e < mq * 32 + 32; e++) {
            float val = o_s[r * CO_VS + e] * dinv;
            pp += val * val;
        }
        red_s[tid] = pp;
        __syncthreads();
        float ms  = (red_s[r * 4 + 0] + red_s[r * 4 + 1] + red_s[r * 4 + 2] + red_s[r * 4 + 3]) * (1.f / 128.f);
        float rms = rsqrtf(ms + 1e-5f);
        #pragma unroll 8
        for (int e = mq * 32; e < mq * 32 + 32; e++) {
            g_o[(size_t)(row0 + r) * DD + col0 + e] = o_s[r * CO_VS + e] * dinv * rms * g_w[e];
        }
    }
}

// ============================================================================
// launch
// ============================================================================
extern "C" void kernel_launch(void* const* d_in, const int* in_sizes, int n_in,
                              void* d_out, int out_size)
{
    const float* x    = (const float*)d_in[0];
    const float* Wq   = (const float*)d_in[1];
    const float* Wk   = (const float*)d_in[2];
    const float* Wv   = (const float*)d_in[3];
    const float* Wo   = (const float*)d_in[4];
    const float* fq1w = (const float*)d_in[5];
    const float* fq1b = (const float*)d_in[6];
    const float* fq2w = (const float*)d_in[7];
    const float* fq2b = (const float*)d_in[8];
    const float* fk1w = (const float*)d_in[9];
    const float* fk1b = (const float*)d_in[10];
    const float* fk2w = (const float*)d_in[11];
    const float* fk2b = (const float*)d_in[12];
    const float* gw   = (const float*)d_in[13];
    float* out = (float*)d_out;

    cudaFuncSetAttribute(qkv_gemm_kernel,      cudaFuncAttributeMaxDynamicSharedMemorySize, MG_SMEM);
    cudaFuncSetAttribute(mma_gemm_kernel,      cudaFuncAttributeMaxDynamicSharedMemorySize, MG_SMEM);
    cudaFuncSetAttribute(featmap_mma_kernel,   cudaFuncAttributeMaxDynamicSharedMemorySize, FM_SMEM);
    cudaFuncSetAttribute(chunk_kv_mma_kernel,  cudaFuncAttributeMaxDynamicSharedMemorySize, KV_SMEM);
    cudaFuncSetAttribute(chunk_out_mma_kernel, cudaFuncAttributeMaxDynamicSharedMemorySize, CO_SMEM);

    float *q_p, *k_p, *v_p, *fq_p, *fk_p, *o_p;
    __nv_bfloat16 *ahi_p, *alo_p, *wthi_p, *wtlo_p, *fwhi_p, *fwlo_p;
    cudaGetSymbolAddress((void**)&q_p,  g_q);
    cudaGetSymbolAddress((void**)&k_p,  g_k);
    cudaGetSymbolAddress((void**)&v_p,  g_v);
    cudaGetSymbolAddress((void**)&fq_p, g_fq);
    cudaGetSymbolAddress((void**)&fk_p, g_fk);
    cudaGetSymbolAddress((void**)&o_p,  g_o);
    cudaGetSymbolAddress((void**)&ahi_p, g_ahi);
    cudaGetSymbolAddress((void**)&alo_p, g_alo);
    cudaGetSymbolAddress((void**)&wthi_p, g_wthi);
    cudaGetSymbolAddress((void**)&wtlo_p, g_wtlo);
    cudaGetSymbolAddress((void**)&fwhi_p, g_fwhi);
    cudaGetSymbolAddress((void**)&fwlo_p, g_fwlo);

    const size_t WSZ = (size_t)DD * DD;
    const int FWSZ = DK * DK;
    dim3 tblk(32, 8), tgrd(32, 32), tgrd128(4, 4);
    transpose_split_kernel<<<tgrd, tblk>>>(Wq, wthi_p + 0 * WSZ, wtlo_p + 0 * WSZ);
    transpose_split_kernel<<<tgrd, tblk>>>(Wk, wthi_p + 1 * WSZ, wtlo_p + 1 * WSZ);
    transpose_split_kernel<<<tgrd, tblk>>>(Wv, wthi_p + 2 * WSZ, wtlo_p + 2 * WSZ);
    transpose_split_kernel<<<tgrd, tblk>>>(Wo, wthi_p + 3 * WSZ, wtlo_p + 3 * WSZ);
    transpose_split128_kernel<<<tgrd128, tblk>>>(fq1w, fwhi_p + 0 * FWSZ, fwlo_p + 0 * FWSZ);
    transpose_split128_kernel<<<tgrd128, tblk>>>(fq2w, fwhi_p + 1 * FWSZ, fwlo_p + 1 * FWSZ);
    transpose_split128_kernel<<<tgrd128, tblk>>>(fk1w, fwhi_p + 2 * FWSZ, fwlo_p + 2 * FWSZ);
    transpose_split128_kernel<<<tgrd128, tblk>>>(fk2w, fwhi_p + 3 * FWSZ, fwlo_p + 3 * FWSZ);

    split_kernel<<<8192, 256>>>(x, ahi_p, alo_p);

    // merged q/k/v GEMM
    qkv_gemm_kernel<<<dim3(24, TTOT / 128), 256, MG_SMEM>>>(
        ahi_p, alo_p, wthi_p, wtlo_p, q_p, k_p, v_p);

    dim3 fgrid(TTOT / 128, HH);
    featmap_mma_kernel<<<fgrid, 256, FM_SMEM>>>(
        q_p, fwhi_p + 0 * FWSZ, fwlo_p + 0 * FWSZ, fwhi_p + 1 * FWSZ, fwlo_p + 1 * FWSZ,
        fq1b, fq2b, fq_p, 0.08838834764831845f);
    featmap_mma_kernel<<<fgrid, 256, FM_SMEM>>>(
        k_p, fwhi_p + 2 * FWSZ, fwlo_p + 2 * FWSZ, fwhi_p + 3 * FWSZ, fwlo_p + 3 * FWSZ,
        fk1b, fk2b, fk_p, 1.0f);

    chunk_kv_mma_kernel<<<dim3(NCH, BHN), 256, KV_SMEM>>>();
    scan_kernel<<<dim3(64, BHN), 256>>>();
    chunk_out_mma_kernel<<<dim3(NCH, BHN), 256, CO_SMEM>>>(gw);

    split_kernel<<<8192, 256>>>(o_p, ahi_p, alo_p);
    mma_gemm_kernel<<<dim3(DD / 128, TTOT / 128), 256, MG_SMEM>>>(
        ahi_p, alo_p, wthi_p + 3 * WSZ, wtlo_p + 3 * WSZ, out);
}